// round 2
// baseline (speedup 1.0000x reference)
#include <cuda_runtime.h>
#include <cuda_bf16.h>

// ---------------------------------------------------------------------------
// Problem constants
// ---------------------------------------------------------------------------
#define BSZ      4
#define SEQ      4096
#define EMB      1024
#define HID      2048           // HIDDEN_DIM
#define FOURH    8192           // 4*HIDDEN
#define NHEADS   16
#define HEADD    128
#define CONVK    4
#define MROWS    (BSZ*SEQ)      // 16384
#define NCH      (BSZ*HID)      // 8192 scan channels

// ---------------------------------------------------------------------------
// Scratch (static device globals; no allocation at runtime)
// ---------------------------------------------------------------------------
__device__ float g_y [(size_t)MROWS * FOURH];   // GEMM1 output  [M, 8192]  512MB
__device__ float g_a [(size_t)NCH   * SEQ];     // scan a        [C, S]     128MB
__device__ float g_b [(size_t)NCH   * SEQ];     // scan b        [C, S]     128MB
__device__ float g_hs[(size_t)NCH   * SEQ];     // scan output   [C, S]     128MB
__device__ float g_g [(size_t)MROWS * HID];     // silu(out1)*out2 [M,2048] 128MB

// ---------------------------------------------------------------------------
// GEMM (NT): C[M,N] = A[M,K] * B[N,K]^T   (both K-major / row-major)
// 128x128 block tile, BK=8, 256 threads, 8x8 per thread.
// ---------------------------------------------------------------------------
__global__ __launch_bounds__(256)
void gemm_nt_kernel(const float* __restrict__ A,
                    const float* __restrict__ B,
                    float* __restrict__ C,
                    int M, int N, int K)
{
    __shared__ float As[8][128];
    __shared__ float Bs[8][128];

    const int bm = blockIdx.y * 128;
    const int bn = blockIdx.x * 128;
    const int tid = threadIdx.x;
    const int tx = tid & 15;        // 0..15 -> n
    const int ty = tid >> 4;        // 0..15 -> m

    const int lr = tid >> 1;        // 0..127 row within tile
    const int lk = (tid & 1) * 4;   // 0 or 4

    const float* Aptr = A + (size_t)(bm + lr) * K + lk;
    const float* Bptr = B + (size_t)(bn + lr) * K + lk;

    float acc[8][8];
#pragma unroll
    for (int i = 0; i < 8; i++)
#pragma unroll
        for (int j = 0; j < 8; j++) acc[i][j] = 0.f;

    for (int k0 = 0; k0 < K; k0 += 8) {
        float4 av = *(const float4*)(Aptr + k0);
        float4 bv = *(const float4*)(Bptr + k0);
        As[lk + 0][lr] = av.x; As[lk + 1][lr] = av.y;
        As[lk + 2][lr] = av.z; As[lk + 3][lr] = av.w;
        Bs[lk + 0][lr] = bv.x; Bs[lk + 1][lr] = bv.y;
        Bs[lk + 2][lr] = bv.z; Bs[lk + 3][lr] = bv.w;
        __syncthreads();

#pragma unroll
        for (int kk = 0; kk < 8; kk++) {
            float ra[8], rb[8];
#pragma unroll
            for (int i = 0; i < 8; i++) ra[i] = As[kk][ty * 8 + i];
#pragma unroll
            for (int j = 0; j < 8; j++) rb[j] = Bs[kk][tx * 8 + j];
#pragma unroll
            for (int i = 0; i < 8; i++)
#pragma unroll
                for (int j = 0; j < 8; j++)
                    acc[i][j] = fmaf(ra[i], rb[j], acc[i][j]);
        }
        __syncthreads();
    }

#pragma unroll
    for (int i = 0; i < 8; i++) {
        float* crow = C + (size_t)(bm + ty * 8 + i) * N + bn + tx * 8;
        float4 v0 = make_float4(acc[i][0], acc[i][1], acc[i][2], acc[i][3]);
        float4 v1 = make_float4(acc[i][4], acc[i][5], acc[i][6], acc[i][7]);
        *(float4*)(crow)     = v0;
        *(float4*)(crow + 4) = v1;
    }
}

// ---------------------------------------------------------------------------
// Conv + gates: from g_y compute a, b in channel-major layout [C, S]
// y row layout: [out1(0..2047) | h(2048..4095) | fi(4096..8191)]
// fi is split per-head AFTER reshape to [B*16, 256, S]:
//   for h-channel c: head hd=c/128, j=c%128
//     f channel (fi-space) fc = hd*256 + j
//     i channel (fi-space) ic = fc + 128
// conv weights cw are indexed in fi-space (rows 0..4095).
// grid: (2048/32, 4096/32, BSZ), block: (32, 8)
// ---------------------------------------------------------------------------
__global__ __launch_bounds__(256)
void conv_gate_kernel(const float* __restrict__ cw)
{
    __shared__ float s_a[32][33];
    __shared__ float s_b[32][33];

    const int c  = blockIdx.x * 32 + threadIdx.x;   // h channel 0..2047
    const int fc = ((c >> 7) << 8) | (c & 127);     // f channel in fi-space
    const int ic = fc + 128;                        // i channel in fi-space
    const int b  = blockIdx.z;
    const int t0 = blockIdx.y * 32;

    float wf[4], wi[4];
#pragma unroll
    for (int k = 0; k < 4; k++) {
        wf[k] = cw[fc * 4 + k];
        wi[k] = cw[ic * 4 + k];
    }

#pragma unroll
    for (int it = 0; it < 4; ++it) {
        const int tl = threadIdx.y + it * 8;
        const int t  = t0 + tl;
        const size_t rowbase = ((size_t)(b * SEQ + t)) * FOURH;

        float accf = 0.f, acci = 0.f;
#pragma unroll
        for (int k = 0; k < 4; k++) {
            int tp = t - 3 + k;
            if (tp >= 0) {
                size_t rb2 = ((size_t)(b * SEQ + tp)) * FOURH;
                accf = fmaf(wf[k], g_y[rb2 + 4096 + fc], accf);
                acci = fmaf(wi[k], g_y[rb2 + 4096 + ic], acci);
            }
        }
        const float h = g_y[rowbase + 2048 + c];
        const float f = 1.f / (1.f + __expf(-accf));
        const float i = 1.f / (1.f + __expf(-acci));
        const float denom = 1.f / (f + i + 1e-4f);
        s_a[tl][threadIdx.x] = f * denom;
        s_b[tl][threadIdx.x] = h * i * denom;
    }
    __syncthreads();

    const int lin = threadIdx.y * 32 + threadIdx.x;
    const int tw  = lin & 31;          // t within tile (coalesced)
    const int cb  = lin >> 5;          // 0..7
#pragma unroll
    for (int j = 0; j < 4; j++) {
        const int cl = cb + j * 8;
        const size_t idx = ((size_t)(b * HID + blockIdx.x * 32 + cl)) * SEQ + t0 + tw;
        g_a[idx] = s_a[tw][cl];
        g_b[idx] = s_b[tw][cl];
    }
}

// ---------------------------------------------------------------------------
// Linear scan per channel: h_t = a_t*h_{t-1} + b_t, h_{-1}=0.
// One block (128 threads) per channel; each thread owns a 32-elem chunk.
// ---------------------------------------------------------------------------
__global__ __launch_bounds__(128)
void scan_kernel()
{
    const int ch  = blockIdx.x;
    const int tid = threadIdx.x;
    const size_t base = (size_t)ch * SEQ + (size_t)tid * 32;

    float a[32], bb[32];
#pragma unroll
    for (int j = 0; j < 32; j += 4) {
        float4 va = *(const float4*)(g_a + base + j);
        float4 vb = *(const float4*)(g_b + base + j);
        a[j + 0] = va.x; a[j + 1] = va.y; a[j + 2] = va.z; a[j + 3] = va.w;
        bb[j + 0] = vb.x; bb[j + 1] = vb.y; bb[j + 2] = vb.z; bb[j + 3] = vb.w;
    }

    // Compose chunk into affine pair (A, B): h_out = A*h_in + B
    float A = 1.f, Bv = 0.f;
#pragma unroll
    for (int j = 0; j < 32; j++) {
        Bv = fmaf(a[j], Bv, bb[j]);
        A *= a[j];
    }

    __shared__ float sA[128], sB[128];
    sA[tid] = A; sB[tid] = Bv;
    __syncthreads();

    for (int off = 1; off < 128; off <<= 1) {
        float pA = 0.f, pB = 0.f;
        if (tid >= off) { pA = sA[tid - off]; pB = sB[tid - off]; }
        __syncthreads();
        if (tid >= off) {
            Bv = fmaf(A, pB, Bv);
            A  = A * pA;
            sA[tid] = A; sB[tid] = Bv;
        }
        __syncthreads();
    }

    float h = (tid == 0) ? 0.f : sB[tid - 1];
#pragma unroll
    for (int j = 0; j < 32; j++) {
        h = fmaf(a[j], h, bb[j]);
        bb[j] = h;                       // reuse regs for output
    }
#pragma unroll
    for (int j = 0; j < 32; j += 4) {
        *(float4*)(g_hs + base + j) = make_float4(bb[j], bb[j + 1], bb[j + 2], bb[j + 3]);
    }
}

// ---------------------------------------------------------------------------
// g = silu(out1) * out2 ; out2 read from channel-major g_hs via smem transpose.
// grid: (2048/32, 4096/32, BSZ), block (32, 8)
// ---------------------------------------------------------------------------
__global__ __launch_bounds__(256)
void silu_mul_kernel()
{
    __shared__ float sm[32][33];
    const int c0 = blockIdx.x * 32;
    const int s0 = blockIdx.y * 32;
    const int b  = blockIdx.z;

    // load g_hs tile: coalesced along s
#pragma unroll
    for (int it = 0; it < 4; ++it) {
        const int cl = threadIdx.y + it * 8;
        const int s  = s0 + threadIdx.x;
        sm[cl][threadIdx.x] = g_hs[((size_t)(b * HID + c0 + cl)) * SEQ + s];
    }
    __syncthreads();

    // write g: coalesced along c
#pragma unroll
    for (int it = 0; it < 4; ++it) {
        const int sl = threadIdx.y + it * 8;
        const int s  = s0 + sl;
        const int c  = c0 + threadIdx.x;
        const size_t row = (size_t)(b * SEQ + s);
        const float o1 = g_y[row * FOURH + c];
        const float sil = o1 / (1.f + __expf(-o1));
        g_g[row * HID + c] = sil * sm[threadIdx.x][sl];
    }
}

// ---------------------------------------------------------------------------
// Launch
// ---------------------------------------------------------------------------
extern "C" void kernel_launch(void* const* d_in, const int* in_sizes, int n_in,
                              void* d_out, int out_size)
{
    const float* x  = (const float*)d_in[0];   // [4,4096,1024]
    const float* w1 = (const float*)d_in[1];   // [8192,1024]
    const float* w2 = (const float*)d_in[2];   // [1024,2048]
    const float* cw = (const float*)d_in[3];   // [4096,4]
    float* out = (float*)d_out;                // [4,4096,1024]

    float *yp, *gp;
    cudaGetSymbolAddress((void**)&yp, g_y);
    cudaGetSymbolAddress((void**)&gp, g_g);

    // GEMM1: y[M,8192] = x[M,1024] @ w1^T
    gemm_nt_kernel<<<dim3(FOURH / 128, MROWS / 128), 256>>>(x, w1, yp, MROWS, FOURH, EMB);

    // conv + gates -> a, b  [C, S]
    conv_gate_kernel<<<dim3(HID / 32, SEQ / 32, BSZ), dim3(32, 8)>>>(cw);

    // linear scan
    scan_kernel<<<NCH, 128>>>();

    // silu(out1) * out2 -> g [M, 2048]
    silu_mul_kernel<<<dim3(HID / 32, SEQ / 32, BSZ), dim3(32, 8)>>>();

    // GEMM2: out[M,1024] = g[M,2048] @ w2^T
    gemm_nt_kernel<<<dim3(EMB / 128, MROWS / 128), 256>>>(gp, w2, out, MROWS, EMB, HID);
}

// round 4
// speedup vs baseline: 2.3692x; 2.3692x over previous
#include <cuda_runtime.h>
#include <cuda_bf16.h>
#include <cstdint>

// ---------------------------------------------------------------------------
// Problem constants
// ---------------------------------------------------------------------------
#define BSZ      4
#define SEQ      4096
#define EMB      1024
#define HID      2048
#define FOURH    8192
#define MROWS    (BSZ*SEQ)      // 16384
#define NCH      (BSZ*HID)      // 8192 scan channels

// GEMM tile config (HMMA mma.sync path — tcgen05 not available at .target sm_103)
#define BM 128
#define BN 128
#define BKK 32
#define ROWB 80                         // padded row stride in bytes (32 bf16 + 16B pad)
#define MAT_BYTES (128*ROWB)            // 10240 per matrix per stage
#define STAGE_BYTES (4*MAT_BYTES)       // Ahi|Alo|Bhi|Blo = 40960
#define NSTAGE 3
#define SMEM_TOTAL_G (NSTAGE*STAGE_BYTES)   // 122880

// ---------------------------------------------------------------------------
// Scratch (static device globals)
// ---------------------------------------------------------------------------
__device__ float g_y [(size_t)MROWS * FOURH];   // GEMM1 out [M,8192] f32
__device__ float g_a [(size_t)NCH   * SEQ];
__device__ float g_b [(size_t)NCH   * SEQ];
__device__ float g_hs[(size_t)NCH   * SEQ];
__device__ __nv_bfloat16 g_xhi[(size_t)MROWS * EMB];
__device__ __nv_bfloat16 g_xlo[(size_t)MROWS * EMB];
__device__ __nv_bfloat16 g_w1hi[(size_t)FOURH * EMB];
__device__ __nv_bfloat16 g_w1lo[(size_t)FOURH * EMB];
__device__ __nv_bfloat16 g_w2hi[(size_t)EMB * HID];
__device__ __nv_bfloat16 g_w2lo[(size_t)EMB * HID];
__device__ __nv_bfloat16 g_ghi[(size_t)MROWS * HID];
__device__ __nv_bfloat16 g_glo[(size_t)MROWS * HID];

// ---------------------------------------------------------------------------
// PTX helpers (all sm_80-baseline: compile at .target sm_103)
// ---------------------------------------------------------------------------
__device__ __forceinline__ uint32_t smem_u32(const void* p) {
    uint32_t a;
    asm("{ .reg .u64 t; cvta.to.shared.u64 t, %1; cvt.u32.u64 %0, t; }" : "=r"(a) : "l"(p));
    return a;
}
__device__ __forceinline__ void cp16(uint32_t s, const void* g) {
    asm volatile("cp.async.cg.shared.global [%0], [%1], 16;" :: "r"(s), "l"(g));
}
#define CP_COMMIT() asm volatile("cp.async.commit_group;" ::: "memory")
#define CP_WAIT(n)  asm volatile("cp.async.wait_group %0;" :: "n"(n) : "memory")

__device__ __forceinline__ void ldsm4(uint32_t& r0, uint32_t& r1, uint32_t& r2, uint32_t& r3,
                                      uint32_t addr) {
    asm volatile("ldmatrix.sync.aligned.m8n8.x4.shared.b16 {%0,%1,%2,%3}, [%4];"
                 : "=r"(r0), "=r"(r1), "=r"(r2), "=r"(r3) : "r"(addr));
}
__device__ __forceinline__ void mma16816(float* c, uint32_t a0, uint32_t a1, uint32_t a2,
                                         uint32_t a3, uint32_t b0, uint32_t b1) {
    asm volatile(
        "mma.sync.aligned.m16n8k16.row.col.f32.bf16.bf16.f32 "
        "{%0,%1,%2,%3}, {%4,%5,%6,%7}, {%8,%9}, {%0,%1,%2,%3};"
        : "+f"(c[0]), "+f"(c[1]), "+f"(c[2]), "+f"(c[3])
        : "r"(a0), "r"(a1), "r"(a2), "r"(a3), "r"(b0), "r"(b1));
}

// ---------------------------------------------------------------------------
// fp32 -> bf16 hi/lo split
// ---------------------------------------------------------------------------
__global__ __launch_bounds__(256)
void split_kernel(const float* __restrict__ in,
                  __nv_bfloat16* __restrict__ hi,
                  __nv_bfloat16* __restrict__ lo, int n4)
{
    int i = blockIdx.x * 256 + threadIdx.x;
    if (i >= n4) return;
    float4 v = ((const float4*)in)[i];
    __nv_bfloat16 h0 = __float2bfloat16_rn(v.x);
    __nv_bfloat16 h1 = __float2bfloat16_rn(v.y);
    __nv_bfloat16 h2 = __float2bfloat16_rn(v.z);
    __nv_bfloat16 h3 = __float2bfloat16_rn(v.w);
    __nv_bfloat162* hp = (__nv_bfloat162*)hi;
    __nv_bfloat162* lp = (__nv_bfloat162*)lo;
    hp[2*i]   = __nv_bfloat162(h0, h1);
    hp[2*i+1] = __nv_bfloat162(h2, h3);
    lp[2*i]   = __nv_bfloat162(__float2bfloat16_rn(v.x - __bfloat162float(h0)),
                               __float2bfloat16_rn(v.y - __bfloat162float(h1)));
    lp[2*i+1] = __nv_bfloat162(__float2bfloat16_rn(v.z - __bfloat162float(h2)),
                               __float2bfloat16_rn(v.w - __bfloat162float(h3)));
}

// ---------------------------------------------------------------------------
// HMMA bf16x3 GEMM: C[M,N] = A[M,K] @ B[N,K]^T, fp32-equivalent precision.
// 128x128 tile, BK=32, 3-stage cp.async pipeline, 256 threads,
// warp grid 4(M)x2(N), warp tile 32x64.
// ---------------------------------------------------------------------------
__global__ __launch_bounds__(256)
void gemm_hmma_kernel(const __nv_bfloat16* __restrict__ Ahi,
                      const __nv_bfloat16* __restrict__ Alo,
                      const __nv_bfloat16* __restrict__ Bhi,
                      const __nv_bfloat16* __restrict__ Blo,
                      float* __restrict__ C, int N, int K)
{
    extern __shared__ char smem[];
    const uint32_t sbase = smem_u32(smem);
    const int tid  = threadIdx.x;
    const int wid  = tid >> 5;
    const int lane = tid & 31;
    const int bm = blockIdx.y * BM;
    const int bn = blockIdx.x * BN;
    const int wm = (wid >> 1) * 32;     // warp m offset 0..96
    const int wn = (wid & 1) * 64;      // warp n offset 0/64

    const int NC = K / BKK;

    // cp.async mapping: q in [0,512): row=q>>2, chunk=q&3 (A); same for B.
    auto load_stage = [&](int kc, int buf) {
        const uint32_t sb = sbase + buf * STAGE_BYTES;
        const int k0 = kc * BKK;
#pragma unroll
        for (int i = 0; i < 2; i++) {
            int q = tid + i * 256;
            int row = q >> 2, ch = q & 3;
            size_t go = (size_t)(bm + row) * K + k0 + ch * 8;
            uint32_t so = sb + row * ROWB + ch * 16;
            cp16(so,               Ahi + go);
            cp16(so + MAT_BYTES,   Alo + go);
        }
#pragma unroll
        for (int i = 0; i < 2; i++) {
            int q = tid + i * 256;
            int row = q >> 2, ch = q & 3;
            size_t go = (size_t)(bn + row) * K + k0 + ch * 8;
            uint32_t so = sb + 2 * MAT_BYTES + row * ROWB + ch * 16;
            cp16(so,               Bhi + go);
            cp16(so + MAT_BYTES,   Blo + go);
        }
    };

    // ldmatrix lane addressing
    const int lr  = lane & 7;
    const int sel = lane >> 3;                     // 0..3
    // A: mats = {rows0-7 k0-7, rows8-15 k0-7, rows0-7 k8-15, rows8-15 k8-15}
    const uint32_t a_lane_off = (uint32_t)((wm + lr + ((sel & 1) << 3)) * ROWB + ((sel >> 1) << 4));
    // B: mats = {n0-7 k0-7, n0-7 k8-15, n8-15 k0-7, n8-15 k8-15}
    const uint32_t b_lane_off = (uint32_t)(2 * MAT_BYTES + (wn + lr + ((sel >> 1) << 3)) * ROWB + ((sel & 1) << 4));

    float acc[2][8][4];
#pragma unroll
    for (int mt = 0; mt < 2; mt++)
#pragma unroll
        for (int nt = 0; nt < 8; nt++)
#pragma unroll
            for (int r = 0; r < 4; r++) acc[mt][nt][r] = 0.f;

    load_stage(0, 0); CP_COMMIT();
    load_stage(1, 1); CP_COMMIT();

    for (int it = 0; it < NC; it++) {
        if (it + 2 < NC) {
            load_stage(it + 2, (it + 2) % NSTAGE); CP_COMMIT();
            CP_WAIT(2);
        } else if (it + 1 < NC) {
            CP_WAIT(1);
        } else {
            CP_WAIT(0);
        }
        __syncthreads();

        const uint32_t sb = sbase + (it % NSTAGE) * STAGE_BYTES;
#pragma unroll
        for (int ks = 0; ks < 2; ks++) {
            const uint32_t kofs = ks * 32;
            uint32_t ah[2][4], al[2][4];
#pragma unroll
            for (int mt = 0; mt < 2; mt++) {
                uint32_t addr = sb + a_lane_off + mt * (16 * ROWB) + kofs;
                ldsm4(ah[mt][0], ah[mt][1], ah[mt][2], ah[mt][3], addr);
                ldsm4(al[mt][0], al[mt][1], al[mt][2], al[mt][3], addr + MAT_BYTES);
            }
            uint32_t bh[4][4], bl[4][4];
#pragma unroll
            for (int ng = 0; ng < 4; ng++) {
                uint32_t addr = sb + b_lane_off + ng * (16 * ROWB) + kofs;
                ldsm4(bh[ng][0], bh[ng][1], bh[ng][2], bh[ng][3], addr);
                ldsm4(bl[ng][0], bl[ng][1], bl[ng][2], bl[ng][3], addr + MAT_BYTES);
            }
#pragma unroll
            for (int mt = 0; mt < 2; mt++) {
#pragma unroll
                for (int nt = 0; nt < 8; nt++) {
                    const int ng = nt >> 1, half = (nt & 1) * 2;
                    uint32_t bh0 = bh[ng][half], bh1 = bh[ng][half + 1];
                    uint32_t bl0 = bl[ng][half], bl1 = bl[ng][half + 1];
                    mma16816(acc[mt][nt], ah[mt][0], ah[mt][1], ah[mt][2], ah[mt][3], bh0, bh1);
                    mma16816(acc[mt][nt], ah[mt][0], ah[mt][1], ah[mt][2], ah[mt][3], bl0, bl1);
                    mma16816(acc[mt][nt], al[mt][0], al[mt][1], al[mt][2], al[mt][3], bh0, bh1);
                }
            }
        }
        __syncthreads();
    }

    // Epilogue: direct fp32 stores
    const int rrow = lane >> 2;
    const int rcol = (lane & 3) * 2;
#pragma unroll
    for (int mt = 0; mt < 2; mt++) {
        const int row0 = bm + wm + mt * 16 + rrow;
#pragma unroll
        for (int nt = 0; nt < 8; nt++) {
            const int col = bn + wn + nt * 8 + rcol;
            *(float2*)(C + (size_t)row0 * N + col)       = make_float2(acc[mt][nt][0], acc[mt][nt][1]);
            *(float2*)(C + (size_t)(row0 + 8) * N + col) = make_float2(acc[mt][nt][2], acc[mt][nt][3]);
        }
    }
}

// ---------------------------------------------------------------------------
// Conv + gates (per-head f/i split), channel-major outputs  [C, S]
// ---------------------------------------------------------------------------
__global__ __launch_bounds__(256)
void conv_gate_kernel(const float* __restrict__ cw)
{
    __shared__ float s_a[32][33];
    __shared__ float s_b[32][33];

    const int c  = blockIdx.x * 32 + threadIdx.x;
    const int fc = ((c >> 7) << 8) | (c & 127);
    const int ic = fc + 128;
    const int b  = blockIdx.z;
    const int t0 = blockIdx.y * 32;

    float wf[4], wi[4];
#pragma unroll
    for (int k = 0; k < 4; k++) { wf[k] = cw[fc * 4 + k]; wi[k] = cw[ic * 4 + k]; }

#pragma unroll
    for (int it = 0; it < 4; ++it) {
        const int tl = threadIdx.y + it * 8;
        const int t  = t0 + tl;
        const size_t rowbase = ((size_t)(b * SEQ + t)) * FOURH;
        float accf = 0.f, acci = 0.f;
#pragma unroll
        for (int k = 0; k < 4; k++) {
            int tp = t - 3 + k;
            if (tp >= 0) {
                size_t rb2 = ((size_t)(b * SEQ + tp)) * FOURH;
                accf = fmaf(wf[k], g_y[rb2 + 4096 + fc], accf);
                acci = fmaf(wi[k], g_y[rb2 + 4096 + ic], acci);
            }
        }
        const float h = g_y[rowbase + 2048 + c];
        const float f = 1.f / (1.f + __expf(-accf));
        const float i = 1.f / (1.f + __expf(-acci));
        const float denom = 1.f / (f + i + 1e-4f);
        s_a[tl][threadIdx.x] = f * denom;
        s_b[tl][threadIdx.x] = h * i * denom;
    }
    __syncthreads();

    const int lin = threadIdx.y * 32 + threadIdx.x;
    const int tw  = lin & 31;
    const int cb  = lin >> 5;
#pragma unroll
    for (int j = 0; j < 4; j++) {
        const int cl = cb + j * 8;
        const size_t idx = ((size_t)(b * HID + blockIdx.x * 32 + cl)) * SEQ + t0 + tw;
        g_a[idx] = s_a[tw][cl];
        g_b[idx] = s_b[tw][cl];
    }
}

// ---------------------------------------------------------------------------
// Linear scan per channel
// ---------------------------------------------------------------------------
__global__ __launch_bounds__(128)
void scan_kernel()
{
    const int ch  = blockIdx.x;
    const int tid = threadIdx.x;
    const size_t base = (size_t)ch * SEQ + (size_t)tid * 32;

    float a[32], bb[32];
#pragma unroll
    for (int j = 0; j < 32; j += 4) {
        float4 va = *(const float4*)(g_a + base + j);
        float4 vb = *(const float4*)(g_b + base + j);
        a[j+0]=va.x; a[j+1]=va.y; a[j+2]=va.z; a[j+3]=va.w;
        bb[j+0]=vb.x; bb[j+1]=vb.y; bb[j+2]=vb.z; bb[j+3]=vb.w;
    }

    float A = 1.f, Bv = 0.f;
#pragma unroll
    for (int j = 0; j < 32; j++) { Bv = fmaf(a[j], Bv, bb[j]); A *= a[j]; }

    __shared__ float sA[128], sB[128];
    sA[tid] = A; sB[tid] = Bv;
    __syncthreads();
    for (int off = 1; off < 128; off <<= 1) {
        float pA = 0.f, pB = 0.f;
        if (tid >= off) { pA = sA[tid - off]; pB = sB[tid - off]; }
        __syncthreads();
        if (tid >= off) { Bv = fmaf(A, pB, Bv); A = A * pA; sA[tid] = A; sB[tid] = Bv; }
        __syncthreads();
    }

    float h = (tid == 0) ? 0.f : sB[tid - 1];
#pragma unroll
    for (int j = 0; j < 32; j++) { h = fmaf(a[j], h, bb[j]); bb[j] = h; }
#pragma unroll
    for (int j = 0; j < 32; j += 4)
        *(float4*)(g_hs + base + j) = make_float4(bb[j], bb[j+1], bb[j+2], bb[j+3]);
}

// ---------------------------------------------------------------------------
// g = silu(out1) * out2 ; writes bf16 hi/lo for GEMM2
// ---------------------------------------------------------------------------
__global__ __launch_bounds__(256)
void silu_mul_kernel()
{
    __shared__ float sm[32][33];
    const int c0 = blockIdx.x * 32;
    const int s0 = blockIdx.y * 32;
    const int b  = blockIdx.z;

#pragma unroll
    for (int it = 0; it < 4; ++it) {
        const int cl = threadIdx.y + it * 8;
        const int s  = s0 + threadIdx.x;
        sm[cl][threadIdx.x] = g_hs[((size_t)(b * HID + c0 + cl)) * SEQ + s];
    }
    __syncthreads();

#pragma unroll
    for (int it = 0; it < 4; ++it) {
        const int sl = threadIdx.y + it * 8;
        const int s  = s0 + sl;
        const int c  = c0 + threadIdx.x;
        const size_t row = (size_t)(b * SEQ + s);
        const float o1 = g_y[row * FOURH + c];
        const float sil = o1 / (1.f + __expf(-o1));
        const float v = sil * sm[threadIdx.x][sl];
        __nv_bfloat16 h = __float2bfloat16_rn(v);
        g_ghi[row * HID + c] = h;
        g_glo[row * HID + c] = __float2bfloat16_rn(v - __bfloat162float(h));
    }
}

// ---------------------------------------------------------------------------
// Launch
// ---------------------------------------------------------------------------
extern "C" void kernel_launch(void* const* d_in, const int* in_sizes, int n_in,
                              void* d_out, int out_size)
{
    const float* x  = (const float*)d_in[0];
    const float* w1 = (const float*)d_in[1];
    const float* w2 = (const float*)d_in[2];
    const float* cw = (const float*)d_in[3];
    float* out = (float*)d_out;

    float *yp;
    cudaGetSymbolAddress((void**)&yp, g_y);
    __nv_bfloat16 *xhi, *xlo, *w1hi, *w1lo, *w2hi, *w2lo, *ghi, *glo;
    cudaGetSymbolAddress((void**)&xhi, g_xhi);
    cudaGetSymbolAddress((void**)&xlo, g_xlo);
    cudaGetSymbolAddress((void**)&w1hi, g_w1hi);
    cudaGetSymbolAddress((void**)&w1lo, g_w1lo);
    cudaGetSymbolAddress((void**)&w2hi, g_w2hi);
    cudaGetSymbolAddress((void**)&w2lo, g_w2lo);
    cudaGetSymbolAddress((void**)&ghi, g_ghi);
    cudaGetSymbolAddress((void**)&glo, g_glo);

    cudaFuncSetAttribute(gemm_hmma_kernel, cudaFuncAttributeMaxDynamicSharedMemorySize, SMEM_TOTAL_G);

    // splits
    {
        int n4 = MROWS * EMB / 4;
        split_kernel<<<(n4 + 255) / 256, 256>>>(x, xhi, xlo, n4);
        n4 = FOURH * EMB / 4;
        split_kernel<<<(n4 + 255) / 256, 256>>>(w1, w1hi, w1lo, n4);
        n4 = EMB * HID / 4;
        split_kernel<<<(n4 + 255) / 256, 256>>>(w2, w2hi, w2lo, n4);
    }

    // GEMM1: y[M,8192] = x @ w1^T
    gemm_hmma_kernel<<<dim3(FOURH / BN, MROWS / BM), 256, SMEM_TOTAL_G>>>(
        xhi, xlo, w1hi, w1lo, yp, FOURH, EMB);

    conv_gate_kernel<<<dim3(HID / 32, SEQ / 32, BSZ), dim3(32, 8)>>>(cw);
    scan_kernel<<<NCH, 128>>>();
    silu_mul_kernel<<<dim3(HID / 32, SEQ / 32, BSZ), dim3(32, 8)>>>();

    // GEMM2: out[M,1024] = g @ w2^T
    gemm_hmma_kernel<<<dim3(EMB / BN, MROWS / BM), 256, SMEM_TOTAL_G>>>(
        ghi, glo, w2hi, w2lo, out, EMB, HID);
}

// round 5
// speedup vs baseline: 2.4316x; 1.0263x over previous
#include <cuda_runtime.h>
#include <cuda_bf16.h>
#include <cstdint>

// ---------------------------------------------------------------------------
// Problem constants
// ---------------------------------------------------------------------------
#define BSZ      4
#define SEQ      4096
#define EMB      1024
#define HID      2048
#define FOURH    8192
#define MROWS    (BSZ*SEQ)      // 16384
#define NCH      (BSZ*HID)      // 8192 scan channels

// GEMM tile config (HMMA mma.sync — tcgen05 unavailable at .target sm_103)
#define BM 128
#define BN 128
#define BKK 32
#define ROWB 80                         // padded row stride in bytes
#define MAT_BYTES (128*ROWB)            // 10240 per matrix per stage
#define STAGE_BYTES (4*MAT_BYTES)       // Ahi|Alo|Bhi|Blo = 40960
#define NSTAGE 3
#define SMEM_TOTAL_G (NSTAGE*STAGE_BYTES)   // 122880
#define GTHREADS 512

// ---------------------------------------------------------------------------
// Scratch (static device globals)
// ---------------------------------------------------------------------------
__device__ float g_y [(size_t)MROWS * FOURH];   // GEMM1 out [M,8192] f32
__device__ float g_a [(size_t)NCH   * SEQ];
__device__ float g_b [(size_t)NCH   * SEQ];
__device__ float g_hs[(size_t)NCH   * SEQ];
__device__ __nv_bfloat16 g_xhi[(size_t)MROWS * EMB];
__device__ __nv_bfloat16 g_xlo[(size_t)MROWS * EMB];
__device__ __nv_bfloat16 g_w1hi[(size_t)FOURH * EMB];
__device__ __nv_bfloat16 g_w1lo[(size_t)FOURH * EMB];
__device__ __nv_bfloat16 g_w2hi[(size_t)EMB * HID];
__device__ __nv_bfloat16 g_w2lo[(size_t)EMB * HID];
__device__ __nv_bfloat16 g_ghi[(size_t)MROWS * HID];
__device__ __nv_bfloat16 g_glo[(size_t)MROWS * HID];

// ---------------------------------------------------------------------------
// PTX helpers (sm_80-baseline)
// ---------------------------------------------------------------------------
__device__ __forceinline__ uint32_t smem_u32(const void* p) {
    uint32_t a;
    asm("{ .reg .u64 t; cvta.to.shared.u64 t, %1; cvt.u32.u64 %0, t; }" : "=r"(a) : "l"(p));
    return a;
}
__device__ __forceinline__ void cp16(uint32_t s, const void* g) {
    asm volatile("cp.async.cg.shared.global [%0], [%1], 16;" :: "r"(s), "l"(g));
}
#define CP_COMMIT() asm volatile("cp.async.commit_group;" ::: "memory")
#define CP_WAIT(n)  asm volatile("cp.async.wait_group %0;" :: "n"(n) : "memory")

__device__ __forceinline__ void ldsm4(uint32_t& r0, uint32_t& r1, uint32_t& r2, uint32_t& r3,
                                      uint32_t addr) {
    asm volatile("ldmatrix.sync.aligned.m8n8.x4.shared.b16 {%0,%1,%2,%3}, [%4];"
                 : "=r"(r0), "=r"(r1), "=r"(r2), "=r"(r3) : "r"(addr));
}
__device__ __forceinline__ void mma16816(float* c, uint32_t a0, uint32_t a1, uint32_t a2,
                                         uint32_t a3, uint32_t b0, uint32_t b1) {
    asm volatile(
        "mma.sync.aligned.m16n8k16.row.col.f32.bf16.bf16.f32 "
        "{%0,%1,%2,%3}, {%4,%5,%6,%7}, {%8,%9}, {%0,%1,%2,%3};"
        : "+f"(c[0]), "+f"(c[1]), "+f"(c[2]), "+f"(c[3])
        : "r"(a0), "r"(a1), "r"(a2), "r"(a3), "r"(b0), "r"(b1));
}

// ---------------------------------------------------------------------------
// fp32 -> bf16 hi/lo split
// ---------------------------------------------------------------------------
__global__ __launch_bounds__(256)
void split_kernel(const float* __restrict__ in,
                  __nv_bfloat16* __restrict__ hi,
                  __nv_bfloat16* __restrict__ lo, int n4)
{
    int i = blockIdx.x * 256 + threadIdx.x;
    if (i >= n4) return;
    float4 v = ((const float4*)in)[i];
    __nv_bfloat16 h0 = __float2bfloat16_rn(v.x);
    __nv_bfloat16 h1 = __float2bfloat16_rn(v.y);
    __nv_bfloat16 h2 = __float2bfloat16_rn(v.z);
    __nv_bfloat16 h3 = __float2bfloat16_rn(v.w);
    __nv_bfloat162* hp = (__nv_bfloat162*)hi;
    __nv_bfloat162* lp = (__nv_bfloat162*)lo;
    hp[2*i]   = __nv_bfloat162(h0, h1);
    hp[2*i+1] = __nv_bfloat162(h2, h3);
    lp[2*i]   = __nv_bfloat162(__float2bfloat16_rn(v.x - __bfloat162float(h0)),
                               __float2bfloat16_rn(v.y - __bfloat162float(h1)));
    lp[2*i+1] = __nv_bfloat162(__float2bfloat16_rn(v.z - __bfloat162float(h2)),
                               __float2bfloat16_rn(v.w - __bfloat162float(h3)));
}

// ---------------------------------------------------------------------------
// HMMA bf16x3 GEMM: C[M,N] = A[M,K] @ B[N,K]^T, fp32-equivalent precision.
// 128x128 tile, BK=32, 3-stage cp.async pipeline, 512 threads,
// warp grid 4(M)x4(N), warp tile 32x32.
// ---------------------------------------------------------------------------
__global__ __launch_bounds__(GTHREADS)
void gemm_hmma_kernel(const __nv_bfloat16* __restrict__ Ahi,
                      const __nv_bfloat16* __restrict__ Alo,
                      const __nv_bfloat16* __restrict__ Bhi,
                      const __nv_bfloat16* __restrict__ Blo,
                      float* __restrict__ C, int N, int K)
{
    extern __shared__ char smem[];
    const uint32_t sbase = smem_u32(smem);
    const int tid  = threadIdx.x;
    const int wid  = tid >> 5;
    const int lane = tid & 31;
    const int bm = blockIdx.y * BM;
    const int bn = blockIdx.x * BN;
    const int wm = (wid >> 2) * 32;     // warp m offset 0..96
    const int wn = (wid & 3) * 32;      // warp n offset 0..96

    const int NC = K / BKK;

    // cp.async: 512 threads, one 16B chunk per matrix per thread.
    const int lrow = tid >> 2;
    const int lch  = tid & 3;
    auto load_stage = [&](int kc, int buf) {
        const uint32_t sb = sbase + buf * STAGE_BYTES;
        const int k0 = kc * BKK;
        {
            size_t go = (size_t)(bm + lrow) * K + k0 + lch * 8;
            uint32_t so = sb + lrow * ROWB + lch * 16;
            cp16(so,             Ahi + go);
            cp16(so + MAT_BYTES, Alo + go);
        }
        {
            size_t go = (size_t)(bn + lrow) * K + k0 + lch * 8;
            uint32_t so = sb + 2 * MAT_BYTES + lrow * ROWB + lch * 16;
            cp16(so,             Bhi + go);
            cp16(so + MAT_BYTES, Blo + go);
        }
    };

    // ldmatrix lane addressing
    const int lr  = lane & 7;
    const int sel = lane >> 3;                     // 0..3
    // A mats: {m0-7 k0-7, m8-15 k0-7, m0-7 k8-15, m8-15 k8-15}
    const uint32_t a_lane_off = (uint32_t)((wm + lr + ((sel & 1) << 3)) * ROWB + ((sel >> 1) << 4));
    // B mats: {n0-7 k0-7, n0-7 k8-15, n8-15 k0-7, n8-15 k8-15}
    const uint32_t b_lane_off = (uint32_t)(2 * MAT_BYTES + (wn + lr + ((sel >> 1) << 3)) * ROWB + ((sel & 1) << 4));

    float acc[2][4][4];
#pragma unroll
    for (int mt = 0; mt < 2; mt++)
#pragma unroll
        for (int nt = 0; nt < 4; nt++)
#pragma unroll
            for (int r = 0; r < 4; r++) acc[mt][nt][r] = 0.f;

    load_stage(0, 0); CP_COMMIT();
    load_stage(1, 1); CP_COMMIT();

    for (int it = 0; it < NC; it++) {
        if (it + 2 < NC) {
            load_stage(it + 2, (it + 2) % NSTAGE); CP_COMMIT();
            CP_WAIT(2);
        } else if (it + 1 < NC) {
            CP_WAIT(1);
        } else {
            CP_WAIT(0);
        }
        __syncthreads();

        const uint32_t sb = sbase + (it % NSTAGE) * STAGE_BYTES;
#pragma unroll
        for (int ks = 0; ks < 2; ks++) {
            const uint32_t kofs = ks * 32;
            uint32_t ah[2][4], al[2][4];
#pragma unroll
            for (int mt = 0; mt < 2; mt++) {
                uint32_t addr = sb + a_lane_off + mt * (16 * ROWB) + kofs;
                ldsm4(ah[mt][0], ah[mt][1], ah[mt][2], ah[mt][3], addr);
                ldsm4(al[mt][0], al[mt][1], al[mt][2], al[mt][3], addr + MAT_BYTES);
            }
            uint32_t bh[2][4], bl[2][4];
#pragma unroll
            for (int ng = 0; ng < 2; ng++) {
                uint32_t addr = sb + b_lane_off + ng * (16 * ROWB) + kofs;
                ldsm4(bh[ng][0], bh[ng][1], bh[ng][2], bh[ng][3], addr);
                ldsm4(bl[ng][0], bl[ng][1], bl[ng][2], bl[ng][3], addr + MAT_BYTES);
            }
#pragma unroll
            for (int mt = 0; mt < 2; mt++) {
#pragma unroll
                for (int nt = 0; nt < 4; nt++) {
                    const int ng = nt >> 1, half = (nt & 1) * 2;
                    uint32_t bh0 = bh[ng][half], bh1 = bh[ng][half + 1];
                    uint32_t bl0 = bl[ng][half], bl1 = bl[ng][half + 1];
                    mma16816(acc[mt][nt], ah[mt][0], ah[mt][1], ah[mt][2], ah[mt][3], bh0, bh1);
                    mma16816(acc[mt][nt], ah[mt][0], ah[mt][1], ah[mt][2], ah[mt][3], bl0, bl1);
                    mma16816(acc[mt][nt], al[mt][0], al[mt][1], al[mt][2], al[mt][3], bh0, bh1);
                }
            }
        }
        __syncthreads();
    }

    // Epilogue: direct fp32 stores
    const int rrow = lane >> 2;
    const int rcol = (lane & 3) * 2;
#pragma unroll
    for (int mt = 0; mt < 2; mt++) {
        const int row0 = bm + wm + mt * 16 + rrow;
#pragma unroll
        for (int nt = 0; nt < 4; nt++) {
            const int col = bn + wn + nt * 8 + rcol;
            *(float2*)(C + (size_t)row0 * N + col)       = make_float2(acc[mt][nt][0], acc[mt][nt][1]);
            *(float2*)(C + (size_t)(row0 + 8) * N + col) = make_float2(acc[mt][nt][2], acc[mt][nt][3]);
        }
    }
}

// ---------------------------------------------------------------------------
// Conv + gates (per-head f/i split), channel-major outputs  [C, S]
// ---------------------------------------------------------------------------
__global__ __launch_bounds__(256)
void conv_gate_kernel(const float* __restrict__ cw)
{
    __shared__ float s_a[32][33];
    __shared__ float s_b[32][33];

    const int c  = blockIdx.x * 32 + threadIdx.x;
    const int fc = ((c >> 7) << 8) | (c & 127);
    const int ic = fc + 128;
    const int b  = blockIdx.z;
    const int t0 = blockIdx.y * 32;

    float wf[4], wi[4];
#pragma unroll
    for (int k = 0; k < 4; k++) { wf[k] = cw[fc * 4 + k]; wi[k] = cw[ic * 4 + k]; }

#pragma unroll
    for (int it = 0; it < 4; ++it) {
        const int tl = threadIdx.y + it * 8;
        const int t  = t0 + tl;
        const size_t rowbase = ((size_t)(b * SEQ + t)) * FOURH;
        float accf = 0.f, acci = 0.f;
#pragma unroll
        for (int k = 0; k < 4; k++) {
            int tp = t - 3 + k;
            if (tp >= 0) {
                size_t rb2 = ((size_t)(b * SEQ + tp)) * FOURH;
                accf = fmaf(wf[k], g_y[rb2 + 4096 + fc], accf);
                acci = fmaf(wi[k], g_y[rb2 + 4096 + ic], acci);
            }
        }
        const float h = g_y[rowbase + 2048 + c];
        const float f = 1.f / (1.f + __expf(-accf));
        const float i = 1.f / (1.f + __expf(-acci));
        const float denom = 1.f / (f + i + 1e-4f);
        s_a[tl][threadIdx.x] = f * denom;
        s_b[tl][threadIdx.x] = h * i * denom;
    }
    __syncthreads();

    const int lin = threadIdx.y * 32 + threadIdx.x;
    const int tw  = lin & 31;
    const int cb  = lin >> 5;
#pragma unroll
    for (int j = 0; j < 4; j++) {
        const int cl = cb + j * 8;
        const size_t idx = ((size_t)(b * HID + blockIdx.x * 32 + cl)) * SEQ + t0 + tw;
        g_a[idx] = s_a[tw][cl];
        g_b[idx] = s_b[tw][cl];
    }
}

// ---------------------------------------------------------------------------
// Linear scan per channel
// ---------------------------------------------------------------------------
__global__ __launch_bounds__(128)
void scan_kernel()
{
    const int ch  = blockIdx.x;
    const int tid = threadIdx.x;
    const size_t base = (size_t)ch * SEQ + (size_t)tid * 32;

    float a[32], bb[32];
#pragma unroll
    for (int j = 0; j < 32; j += 4) {
        float4 va = *(const float4*)(g_a + base + j);
        float4 vb = *(const float4*)(g_b + base + j);
        a[j+0]=va.x; a[j+1]=va.y; a[j+2]=va.z; a[j+3]=va.w;
        bb[j+0]=vb.x; bb[j+1]=vb.y; bb[j+2]=vb.z; bb[j+3]=vb.w;
    }

    float A = 1.f, Bv = 0.f;
#pragma unroll
    for (int j = 0; j < 32; j++) { Bv = fmaf(a[j], Bv, bb[j]); A *= a[j]; }

    __shared__ float sA[128], sB[128];
    sA[tid] = A; sB[tid] = Bv;
    __syncthreads();
    for (int off = 1; off < 128; off <<= 1) {
        float pA = 0.f, pB = 0.f;
        if (tid >= off) { pA = sA[tid - off]; pB = sB[tid - off]; }
        __syncthreads();
        if (tid >= off) { Bv = fmaf(A, pB, Bv); A = A * pA; sA[tid] = A; sB[tid] = Bv; }
        __syncthreads();
    }

    float h = (tid == 0) ? 0.f : sB[tid - 1];
#pragma unroll
    for (int j = 0; j < 32; j++) { h = fmaf(a[j], h, bb[j]); bb[j] = h; }
#pragma unroll
    for (int j = 0; j < 32; j += 4)
        *(float4*)(g_hs + base + j) = make_float4(bb[j], bb[j+1], bb[j+2], bb[j+3]);
}

// ---------------------------------------------------------------------------
// g = silu(out1) * out2 ; writes bf16 hi/lo for GEMM2
// ---------------------------------------------------------------------------
__global__ __launch_bounds__(256)
void silu_mul_kernel()
{
    __shared__ float sm[32][33];
    const int c0 = blockIdx.x * 32;
    const int s0 = blockIdx.y * 32;
    const int b  = blockIdx.z;

#pragma unroll
    for (int it = 0; it < 4; ++it) {
        const int cl = threadIdx.y + it * 8;
        const int s  = s0 + threadIdx.x;
        sm[cl][threadIdx.x] = g_hs[((size_t)(b * HID + c0 + cl)) * SEQ + s];
    }
    __syncthreads();

#pragma unroll
    for (int it = 0; it < 4; ++it) {
        const int sl = threadIdx.y + it * 8;
        const int s  = s0 + sl;
        const int c  = c0 + threadIdx.x;
        const size_t row = (size_t)(b * SEQ + s);
        const float o1 = g_y[row * FOURH + c];
        const float sil = o1 / (1.f + __expf(-o1));
        const float v = sil * sm[threadIdx.x][sl];
        __nv_bfloat16 h = __float2bfloat16_rn(v);
        g_ghi[row * HID + c] = h;
        g_glo[row * HID + c] = __float2bfloat16_rn(v - __bfloat162float(h));
    }
}

// ---------------------------------------------------------------------------
// Launch
// ---------------------------------------------------------------------------
extern "C" void kernel_launch(void* const* d_in, const int* in_sizes, int n_in,
                              void* d_out, int out_size)
{
    const float* x  = (const float*)d_in[0];
    const float* w1 = (const float*)d_in[1];
    const float* w2 = (const float*)d_in[2];
    const float* cw = (const float*)d_in[3];
    float* out = (float*)d_out;

    float *yp;
    cudaGetSymbolAddress((void**)&yp, g_y);
    __nv_bfloat16 *xhi, *xlo, *w1hi, *w1lo, *w2hi, *w2lo, *ghi, *glo;
    cudaGetSymbolAddress((void**)&xhi, g_xhi);
    cudaGetSymbolAddress((void**)&xlo, g_xlo);
    cudaGetSymbolAddress((void**)&w1hi, g_w1hi);
    cudaGetSymbolAddress((void**)&w1lo, g_w1lo);
    cudaGetSymbolAddress((void**)&w2hi, g_w2hi);
    cudaGetSymbolAddress((void**)&w2lo, g_w2lo);
    cudaGetSymbolAddress((void**)&ghi, g_ghi);
    cudaGetSymbolAddress((void**)&glo, g_glo);

    cudaFuncSetAttribute(gemm_hmma_kernel, cudaFuncAttributeMaxDynamicSharedMemorySize, SMEM_TOTAL_G);

    // splits
    {
        int n4 = MROWS * EMB / 4;
        split_kernel<<<(n4 + 255) / 256, 256>>>(x, xhi, xlo, n4);
        n4 = FOURH * EMB / 4;
        split_kernel<<<(n4 + 255) / 256, 256>>>(w1, w1hi, w1lo, n4);
        n4 = EMB * HID / 4;
        split_kernel<<<(n4 + 255) / 256, 256>>>(w2, w2hi, w2lo, n4);
    }

    // GEMM1: y[M,8192] = x @ w1^T
    gemm_hmma_kernel<<<dim3(FOURH / BN, MROWS / BM), GTHREADS, SMEM_TOTAL_G>>>(
        xhi, xlo, w1hi, w1lo, yp, FOURH, EMB);

    conv_gate_kernel<<<dim3(HID / 32, SEQ / 32, BSZ), dim3(32, 8)>>>(cw);
    scan_kernel<<<NCH, 128>>>();
    silu_mul_kernel<<<dim3(HID / 32, SEQ / 32, BSZ), dim3(32, 8)>>>();

    // GEMM2: out[M,1024] = g @ w2^T
    gemm_hmma_kernel<<<dim3(EMB / BN, MROWS / BM), GTHREADS, SMEM_TOTAL_G>>>(
        ghi, glo, w2hi, w2lo, out, EMB, HID);
}

// round 6
// speedup vs baseline: 2.6168x; 1.0762x over previous
#include <cuda_runtime.h>
#include <cuda_bf16.h>
#include <cstdint>

// ---------------------------------------------------------------------------
// Problem constants
// ---------------------------------------------------------------------------
#define BSZ      4
#define SEQ      4096
#define EMB      1024
#define HID      2048
#define FOURH    8192
#define MROWS    (BSZ*SEQ)      // 16384
#define NCH      (BSZ*HID)      // 8192 scan channels

// GEMM tile config (HMMA mma.sync — tcgen05 unavailable at .target sm_103)
#define BM 128
#define BN 256
#define BKK 32
#define ROWB 80                         // padded smem row stride (64B data + 16B pad)
#define A_MAT (128*ROWB)                // 10240
#define B_MAT (256*ROWB)                // 20480
// stage layout: Ahi 0 | Alo 10240 | Bhi 20480 | Blo 40960
#define B_OFF (2*A_MAT)
#define STAGE_BYTES (2*A_MAT + 2*B_MAT) // 61440
#define NSTAGE 2
#define SMEM_TOTAL_G (NSTAGE*STAGE_BYTES)   // 122880
#define GTHREADS 256

// ---------------------------------------------------------------------------
// Scratch (static device globals)
// ---------------------------------------------------------------------------
__device__ float g_y [(size_t)MROWS * FOURH];
__device__ float g_a [(size_t)NCH   * SEQ];
__device__ float g_b [(size_t)NCH   * SEQ];
__device__ float g_hs[(size_t)NCH   * SEQ];
__device__ __nv_bfloat16 g_xhi[(size_t)MROWS * EMB];
__device__ __nv_bfloat16 g_xlo[(size_t)MROWS * EMB];
__device__ __nv_bfloat16 g_w1hi[(size_t)FOURH * EMB];
__device__ __nv_bfloat16 g_w1lo[(size_t)FOURH * EMB];
__device__ __nv_bfloat16 g_w2hi[(size_t)EMB * HID];
__device__ __nv_bfloat16 g_w2lo[(size_t)EMB * HID];
__device__ __nv_bfloat16 g_ghi[(size_t)MROWS * HID];
__device__ __nv_bfloat16 g_glo[(size_t)MROWS * HID];

// ---------------------------------------------------------------------------
// PTX helpers (sm_80-baseline)
// ---------------------------------------------------------------------------
__device__ __forceinline__ uint32_t smem_u32(const void* p) {
    uint32_t a;
    asm("{ .reg .u64 t; cvta.to.shared.u64 t, %1; cvt.u32.u64 %0, t; }" : "=r"(a) : "l"(p));
    return a;
}
__device__ __forceinline__ void cp16(uint32_t s, const void* g) {
    asm volatile("cp.async.cg.shared.global [%0], [%1], 16;" :: "r"(s), "l"(g));
}
#define CP_COMMIT() asm volatile("cp.async.commit_group;" ::: "memory")
#define CP_WAIT(n)  asm volatile("cp.async.wait_group %0;" :: "n"(n) : "memory")

__device__ __forceinline__ void ldsm4(uint32_t& r0, uint32_t& r1, uint32_t& r2, uint32_t& r3,
                                      uint32_t addr) {
    asm volatile("ldmatrix.sync.aligned.m8n8.x4.shared.b16 {%0,%1,%2,%3}, [%4];"
                 : "=r"(r0), "=r"(r1), "=r"(r2), "=r"(r3) : "r"(addr));
}
__device__ __forceinline__ void mma16816(float* c, uint32_t a0, uint32_t a1, uint32_t a2,
                                         uint32_t a3, uint32_t b0, uint32_t b1) {
    asm volatile(
        "mma.sync.aligned.m16n8k16.row.col.f32.bf16.bf16.f32 "
        "{%0,%1,%2,%3}, {%4,%5,%6,%7}, {%8,%9}, {%0,%1,%2,%3};"
        : "+f"(c[0]), "+f"(c[1]), "+f"(c[2]), "+f"(c[3])
        : "r"(a0), "r"(a1), "r"(a2), "r"(a3), "r"(b0), "r"(b1));
}

// ---------------------------------------------------------------------------
// fp32 -> bf16 hi/lo split
// ---------------------------------------------------------------------------
__global__ __launch_bounds__(256)
void split_kernel(const float* __restrict__ in,
                  __nv_bfloat16* __restrict__ hi,
                  __nv_bfloat16* __restrict__ lo, int n4)
{
    int i = blockIdx.x * 256 + threadIdx.x;
    if (i >= n4) return;
    float4 v = ((const float4*)in)[i];
    __nv_bfloat16 h0 = __float2bfloat16_rn(v.x);
    __nv_bfloat16 h1 = __float2bfloat16_rn(v.y);
    __nv_bfloat16 h2 = __float2bfloat16_rn(v.z);
    __nv_bfloat16 h3 = __float2bfloat16_rn(v.w);
    __nv_bfloat162* hp = (__nv_bfloat162*)hi;
    __nv_bfloat162* lp = (__nv_bfloat162*)lo;
    hp[2*i]   = __nv_bfloat162(h0, h1);
    hp[2*i+1] = __nv_bfloat162(h2, h3);
    lp[2*i]   = __nv_bfloat162(__float2bfloat16_rn(v.x - __bfloat162float(h0)),
                               __float2bfloat16_rn(v.y - __bfloat162float(h1)));
    lp[2*i+1] = __nv_bfloat162(__float2bfloat16_rn(v.z - __bfloat162float(h2)),
                               __float2bfloat16_rn(v.w - __bfloat162float(h3)));
}

// ---------------------------------------------------------------------------
// HMMA bf16x3 GEMM: C[M,N] = A[M,K] @ B[N,K]^T, fp32-equivalent precision.
// CTA tile 128x256, BK=32, 2-stage cp.async pipeline, 256 threads,
// warp grid 2(M)x4(N), warp tile 64x64.
// ---------------------------------------------------------------------------
__global__ __launch_bounds__(GTHREADS)
void gemm_hmma_kernel(const __nv_bfloat16* __restrict__ Ahi,
                      const __nv_bfloat16* __restrict__ Alo,
                      const __nv_bfloat16* __restrict__ Bhi,
                      const __nv_bfloat16* __restrict__ Blo,
                      float* __restrict__ C, int N, int K)
{
    extern __shared__ char smem[];
    const uint32_t sbase = smem_u32(smem);
    const int tid  = threadIdx.x;
    const int wid  = tid >> 5;
    const int lane = tid & 31;
    const int bm = blockIdx.y * BM;
    const int bn = blockIdx.x * BN;
    const int wm = (wid >> 2) * 64;     // warp m offset: 0 or 64
    const int wn = (wid & 3) * 64;      // warp n offset: 0..192

    const int NC = K / BKK;

    // cp.async: 256 threads. A: 128 rows x 4 chunks (2 rows/thread);
    // B: 256 rows x 4 chunks (4 rows/thread). hi+lo each.
    const int lrow = tid >> 2;          // 0..63
    const int lch  = tid & 3;
    auto load_stage = [&](int kc, int buf) {
        const uint32_t sb = sbase + buf * STAGE_BYTES;
        const int k0 = kc * BKK;
#pragma unroll
        for (int j = 0; j < 2; j++) {
            int r = lrow + j * 64;
            size_t go = (size_t)(bm + r) * K + k0 + lch * 8;
            uint32_t so = sb + r * ROWB + lch * 16;
            cp16(so,         Ahi + go);
            cp16(so + A_MAT, Alo + go);
        }
#pragma unroll
        for (int j = 0; j < 4; j++) {
            int r = lrow + j * 64;
            size_t go = (size_t)(bn + r) * K + k0 + lch * 8;
            uint32_t so = sb + B_OFF + r * ROWB + lch * 16;
            cp16(so,         Bhi + go);
            cp16(so + B_MAT, Blo + go);
        }
    };

    // ldmatrix lane addressing
    const int lr  = lane & 7;
    const int sel = lane >> 3;                     // 0..3
    // A mats: {m0-7 k0-7, m8-15 k0-7, m0-7 k8-15, m8-15 k8-15}
    const uint32_t a_lane_off = (uint32_t)((wm + lr + ((sel & 1) << 3)) * ROWB + ((sel >> 1) << 4));
    // B mats: {n0-7 k0-7, n0-7 k8-15, n8-15 k0-7, n8-15 k8-15}
    const uint32_t b_lane_off = (uint32_t)(B_OFF + (wn + lr + ((sel >> 1) << 3)) * ROWB + ((sel & 1) << 4));

    float acc[4][8][4];
#pragma unroll
    for (int mt = 0; mt < 4; mt++)
#pragma unroll
        for (int nt = 0; nt < 8; nt++)
#pragma unroll
            for (int r = 0; r < 4; r++) acc[mt][nt][r] = 0.f;

    load_stage(0, 0); CP_COMMIT();
    load_stage(1, 1); CP_COMMIT();

    for (int it = 0; it < NC; it++) {
        CP_WAIT(1);
        __syncthreads();

        const uint32_t sb = sbase + (it & 1) * STAGE_BYTES;
#pragma unroll
        for (int ks = 0; ks < 2; ks++) {
            const uint32_t kofs = ks * 32;
            uint32_t ah[4][4], al[4][4];
#pragma unroll
            for (int mt = 0; mt < 4; mt++) {
                uint32_t addr = sb + a_lane_off + mt * (16 * ROWB) + kofs;
                ldsm4(ah[mt][0], ah[mt][1], ah[mt][2], ah[mt][3], addr);
                ldsm4(al[mt][0], al[mt][1], al[mt][2], al[mt][3], addr + A_MAT);
            }
#pragma unroll
            for (int ng = 0; ng < 4; ng++) {
                uint32_t bh[4], bl[4];
                uint32_t addr = sb + b_lane_off + ng * (16 * ROWB) + kofs;
                ldsm4(bh[0], bh[1], bh[2], bh[3], addr);
                ldsm4(bl[0], bl[1], bl[2], bl[3], addr + B_MAT);
#pragma unroll
                for (int mt = 0; mt < 4; mt++) {
#pragma unroll
                    for (int half = 0; half < 2; half++) {
                        float* a4 = acc[mt][ng * 2 + half];
                        uint32_t bh0 = bh[half*2], bh1 = bh[half*2+1];
                        uint32_t bl0 = bl[half*2], bl1 = bl[half*2+1];
                        mma16816(a4, ah[mt][0], ah[mt][1], ah[mt][2], ah[mt][3], bh0, bh1);
                        mma16816(a4, ah[mt][0], ah[mt][1], ah[mt][2], ah[mt][3], bl0, bl1);
                        mma16816(a4, al[mt][0], al[mt][1], al[mt][2], al[mt][3], bh0, bh1);
                    }
                }
            }
        }
        __syncthreads();
        if (it + 2 < NC) { load_stage(it + 2, it & 1); CP_COMMIT(); }
        else { CP_COMMIT(); }   // keep group count consistent for CP_WAIT(1)
    }

    // Epilogue: direct fp32 stores
    const int rrow = lane >> 2;
    const int rcol = (lane & 3) * 2;
#pragma unroll
    for (int mt = 0; mt < 4; mt++) {
        const int row0 = bm + wm + mt * 16 + rrow;
#pragma unroll
        for (int nt = 0; nt < 8; nt++) {
            const int col = bn + wn + nt * 8 + rcol;
            *(float2*)(C + (size_t)row0 * N + col)       = make_float2(acc[mt][nt][0], acc[mt][nt][1]);
            *(float2*)(C + (size_t)(row0 + 8) * N + col) = make_float2(acc[mt][nt][2], acc[mt][nt][3]);
        }
    }
}

// ---------------------------------------------------------------------------
// Conv + gates (per-head f/i split), channel-major outputs  [C, S]
// ---------------------------------------------------------------------------
__global__ __launch_bounds__(256)
void conv_gate_kernel(const float* __restrict__ cw)
{
    __shared__ float s_a[32][33];
    __shared__ float s_b[32][33];

    const int c  = blockIdx.x * 32 + threadIdx.x;
    const int fc = ((c >> 7) << 8) | (c & 127);
    const int ic = fc + 128;
    const int b  = blockIdx.z;
    const int t0 = blockIdx.y * 32;

    float wf[4], wi[4];
#pragma unroll
    for (int k = 0; k < 4; k++) { wf[k] = cw[fc * 4 + k]; wi[k] = cw[ic * 4 + k]; }

#pragma unroll
    for (int it = 0; it < 4; ++it) {
        const int tl = threadIdx.y + it * 8;
        const int t  = t0 + tl;
        const size_t rowbase = ((size_t)(b * SEQ + t)) * FOURH;
        float accf = 0.f, acci = 0.f;
#pragma unroll
        for (int k = 0; k < 4; k++) {
            int tp = t - 3 + k;
            if (tp >= 0) {
                size_t rb2 = ((size_t)(b * SEQ + tp)) * FOURH;
                accf = fmaf(wf[k], g_y[rb2 + 4096 + fc], accf);
                acci = fmaf(wi[k], g_y[rb2 + 4096 + ic], acci);
            }
        }
        const float h = g_y[rowbase + 2048 + c];
        const float f = 1.f / (1.f + __expf(-accf));
        const float i = 1.f / (1.f + __expf(-acci));
        const float denom = 1.f / (f + i + 1e-4f);
        s_a[tl][threadIdx.x] = f * denom;
        s_b[tl][threadIdx.x] = h * i * denom;
    }
    __syncthreads();

    const int lin = threadIdx.y * 32 + threadIdx.x;
    const int tw  = lin & 31;
    const int cb  = lin >> 5;
#pragma unroll
    for (int j = 0; j < 4; j++) {
        const int cl = cb + j * 8;
        const size_t idx = ((size_t)(b * HID + blockIdx.x * 32 + cl)) * SEQ + t0 + tw;
        g_a[idx] = s_a[tw][cl];
        g_b[idx] = s_b[tw][cl];
    }
}

// ---------------------------------------------------------------------------
// Linear scan per channel
// ---------------------------------------------------------------------------
__global__ __launch_bounds__(128)
void scan_kernel()
{
    const int ch  = blockIdx.x;
    const int tid = threadIdx.x;
    const size_t base = (size_t)ch * SEQ + (size_t)tid * 32;

    float a[32], bb[32];
#pragma unroll
    for (int j = 0; j < 32; j += 4) {
        float4 va = *(const float4*)(g_a + base + j);
        float4 vb = *(const float4*)(g_b + base + j);
        a[j+0]=va.x; a[j+1]=va.y; a[j+2]=va.z; a[j+3]=va.w;
        bb[j+0]=vb.x; bb[j+1]=vb.y; bb[j+2]=vb.z; bb[j+3]=vb.w;
    }

    float A = 1.f, Bv = 0.f;
#pragma unroll
    for (int j = 0; j < 32; j++) { Bv = fmaf(a[j], Bv, bb[j]); A *= a[j]; }

    __shared__ float sA[128], sB[128];
    sA[tid] = A; sB[tid] = Bv;
    __syncthreads();
    for (int off = 1; off < 128; off <<= 1) {
        float pA = 0.f, pB = 0.f;
        if (tid >= off) { pA = sA[tid - off]; pB = sB[tid - off]; }
        __syncthreads();
        if (tid >= off) { Bv = fmaf(A, pB, Bv); A = A * pA; sA[tid] = A; sB[tid] = Bv; }
        __syncthreads();
    }

    float h = (tid == 0) ? 0.f : sB[tid - 1];
#pragma unroll
    for (int j = 0; j < 32; j++) { h = fmaf(a[j], h, bb[j]); bb[j] = h; }
#pragma unroll
    for (int j = 0; j < 32; j += 4)
        *(float4*)(g_hs + base + j) = make_float4(bb[j], bb[j+1], bb[j+2], bb[j+3]);
}

// ---------------------------------------------------------------------------
// g = silu(out1) * out2 ; writes bf16 hi/lo for GEMM2
// ---------------------------------------------------------------------------
__global__ __launch_bounds__(256)
void silu_mul_kernel()
{
    __shared__ float sm[32][33];
    const int c0 = blockIdx.x * 32;
    const int s0 = blockIdx.y * 32;
    const int b  = blockIdx.z;

#pragma unroll
    for (int it = 0; it < 4; ++it) {
        const int cl = threadIdx.y + it * 8;
        const int s  = s0 + threadIdx.x;
        sm[cl][threadIdx.x] = g_hs[((size_t)(b * HID + c0 + cl)) * SEQ + s];
    }
    __syncthreads();

#pragma unroll
    for (int it = 0; it < 4; ++it) {
        const int sl = threadIdx.y + it * 8;
        const int s  = s0 + sl;
        const int c  = c0 + threadIdx.x;
        const size_t row = (size_t)(b * SEQ + s);
        const float o1 = g_y[row * FOURH + c];
        const float sil = o1 / (1.f + __expf(-o1));
        const float v = sil * sm[threadIdx.x][sl];
        __nv_bfloat16 h = __float2bfloat16_rn(v);
        g_ghi[row * HID + c] = h;
        g_glo[row * HID + c] = __float2bfloat16_rn(v - __bfloat162float(h));
    }
}

// ---------------------------------------------------------------------------
// Launch
// ---------------------------------------------------------------------------
extern "C" void kernel_launch(void* const* d_in, const int* in_sizes, int n_in,
                              void* d_out, int out_size)
{
    const float* x  = (const float*)d_in[0];
    const float* w1 = (const float*)d_in[1];
    const float* w2 = (const float*)d_in[2];
    const float* cw = (const float*)d_in[3];
    float* out = (float*)d_out;

    float *yp;
    cudaGetSymbolAddress((void**)&yp, g_y);
    __nv_bfloat16 *xhi, *xlo, *w1hi, *w1lo, *w2hi, *w2lo, *ghi, *glo;
    cudaGetSymbolAddress((void**)&xhi, g_xhi);
    cudaGetSymbolAddress((void**)&xlo, g_xlo);
    cudaGetSymbolAddress((void**)&w1hi, g_w1hi);
    cudaGetSymbolAddress((void**)&w1lo, g_w1lo);
    cudaGetSymbolAddress((void**)&w2hi, g_w2hi);
    cudaGetSymbolAddress((void**)&w2lo, g_w2lo);
    cudaGetSymbolAddress((void**)&ghi, g_ghi);
    cudaGetSymbolAddress((void**)&glo, g_glo);

    cudaFuncSetAttribute(gemm_hmma_kernel, cudaFuncAttributeMaxDynamicSharedMemorySize, SMEM_TOTAL_G);

    // splits
    {
        int n4 = MROWS * EMB / 4;
        split_kernel<<<(n4 + 255) / 256, 256>>>(x, xhi, xlo, n4);
        n4 = FOURH * EMB / 4;
        split_kernel<<<(n4 + 255) / 256, 256>>>(w1, w1hi, w1lo, n4);
        n4 = EMB * HID / 4;
        split_kernel<<<(n4 + 255) / 256, 256>>>(w2, w2hi, w2lo, n4);
    }

    // GEMM1: y[M,8192] = x @ w1^T
    gemm_hmma_kernel<<<dim3(FOURH / BN, MROWS / BM), GTHREADS, SMEM_TOTAL_G>>>(
        xhi, xlo, w1hi, w1lo, yp, FOURH, EMB);

    conv_gate_kernel<<<dim3(HID / 32, SEQ / 32, BSZ), dim3(32, 8)>>>(cw);
    scan_kernel<<<NCH, 128>>>();
    silu_mul_kernel<<<dim3(HID / 32, SEQ / 32, BSZ), dim3(32, 8)>>>();

    // GEMM2: out[M,1024] = g @ w2^T
    gemm_hmma_kernel<<<dim3(EMB / BN, MROWS / BM), GTHREADS, SMEM_TOTAL_G>>>(
        ghi, glo, w2hi, w2lo, out, EMB, HID);
}

// round 7
// speedup vs baseline: 2.6446x; 1.0106x over previous
#include <cuda_runtime.h>
#include <cuda_bf16.h>
#include <cstdint>

// ---------------------------------------------------------------------------
// Problem constants
// ---------------------------------------------------------------------------
#define BSZ      4
#define SEQ      4096
#define EMB      1024
#define HID      2048
#define FOURH    8192
#define MROWS    (BSZ*SEQ)      // 16384
#define NCH      (BSZ*HID)      // 8192 scan channels

// GEMM tile config (HMMA mma.sync — tcgen05 unavailable at .target sm_103)
#define BM 128
#define BN 256
#define BKK 32
#define ROWB 80                         // padded smem row stride (64B data + 16B pad)
#define A_MAT (128*ROWB)                // 10240
#define B_MAT (256*ROWB)                // 20480
#define B_OFF (2*A_MAT)
#define STAGE_BYTES (2*A_MAT + 2*B_MAT) // 61440
#define NSTAGE 3
#define SMEM_TOTAL_G (NSTAGE*STAGE_BYTES)   // 184320
#define GTHREADS 256

// ---------------------------------------------------------------------------
// Scratch (static device globals)
// ---------------------------------------------------------------------------
__device__ float g_y [(size_t)MROWS * FOURH];
__device__ float g_a [(size_t)NCH   * SEQ];
__device__ float g_b [(size_t)NCH   * SEQ];
__device__ float g_hs[(size_t)NCH   * SEQ];
__device__ __nv_bfloat16 g_xhi[(size_t)MROWS * EMB];
__device__ __nv_bfloat16 g_xlo[(size_t)MROWS * EMB];
__device__ __nv_bfloat16 g_w1hi[(size_t)FOURH * EMB];
__device__ __nv_bfloat16 g_w1lo[(size_t)FOURH * EMB];
__device__ __nv_bfloat16 g_w2hi[(size_t)EMB * HID];
__device__ __nv_bfloat16 g_w2lo[(size_t)EMB * HID];
__device__ __nv_bfloat16 g_ghi[(size_t)MROWS * HID];
__device__ __nv_bfloat16 g_glo[(size_t)MROWS * HID];

// ---------------------------------------------------------------------------
// PTX helpers (sm_80-baseline)
// ---------------------------------------------------------------------------
__device__ __forceinline__ uint32_t smem_u32(const void* p) {
    uint32_t a;
    asm("{ .reg .u64 t; cvta.to.shared.u64 t, %1; cvt.u32.u64 %0, t; }" : "=r"(a) : "l"(p));
    return a;
}
__device__ __forceinline__ void cp16(uint32_t s, const void* g) {
    asm volatile("cp.async.cg.shared.global [%0], [%1], 16;" :: "r"(s), "l"(g));
}
#define CP_COMMIT() asm volatile("cp.async.commit_group;" ::: "memory")
#define CP_WAIT(n)  asm volatile("cp.async.wait_group %0;" :: "n"(n) : "memory")

__device__ __forceinline__ void ldsm4(uint32_t& r0, uint32_t& r1, uint32_t& r2, uint32_t& r3,
                                      uint32_t addr) {
    asm volatile("ldmatrix.sync.aligned.m8n8.x4.shared.b16 {%0,%1,%2,%3}, [%4];"
                 : "=r"(r0), "=r"(r1), "=r"(r2), "=r"(r3) : "r"(addr));
}
__device__ __forceinline__ void mma16816(float* c, uint32_t a0, uint32_t a1, uint32_t a2,
                                         uint32_t a3, uint32_t b0, uint32_t b1) {
    asm volatile(
        "mma.sync.aligned.m16n8k16.row.col.f32.bf16.bf16.f32 "
        "{%0,%1,%2,%3}, {%4,%5,%6,%7}, {%8,%9}, {%0,%1,%2,%3};"
        : "+f"(c[0]), "+f"(c[1]), "+f"(c[2]), "+f"(c[3])
        : "r"(a0), "r"(a1), "r"(a2), "r"(a3), "r"(b0), "r"(b1));
}

// ---------------------------------------------------------------------------
// fp32 -> bf16 hi/lo split
// ---------------------------------------------------------------------------
__global__ __launch_bounds__(256)
void split_kernel(const float* __restrict__ in,
                  __nv_bfloat16* __restrict__ hi,
                  __nv_bfloat16* __restrict__ lo, int n4)
{
    int i = blockIdx.x * 256 + threadIdx.x;
    if (i >= n4) return;
    float4 v = ((const float4*)in)[i];
    __nv_bfloat16 h0 = __float2bfloat16_rn(v.x);
    __nv_bfloat16 h1 = __float2bfloat16_rn(v.y);
    __nv_bfloat16 h2 = __float2bfloat16_rn(v.z);
    __nv_bfloat16 h3 = __float2bfloat16_rn(v.w);
    __nv_bfloat162* hp = (__nv_bfloat162*)hi;
    __nv_bfloat162* lp = (__nv_bfloat162*)lo;
    hp[2*i]   = __nv_bfloat162(h0, h1);
    hp[2*i+1] = __nv_bfloat162(h2, h3);
    lp[2*i]   = __nv_bfloat162(__float2bfloat16_rn(v.x - __bfloat162float(h0)),
                               __float2bfloat16_rn(v.y - __bfloat162float(h1)));
    lp[2*i+1] = __nv_bfloat162(__float2bfloat16_rn(v.z - __bfloat162float(h2)),
                               __float2bfloat16_rn(v.w - __bfloat162float(h3)));
}

// ---------------------------------------------------------------------------
// HMMA bf16x3 GEMM: C[M,N] = A[M,K] @ B[N,K]^T, fp32-equivalent precision.
// CTA tile 128x256, BK=32, 3-stage cp.async pipeline (1 sync/iter),
// 256 threads, warp grid 2(M)x4(N), warp tile 64x64.
// ---------------------------------------------------------------------------
__global__ __launch_bounds__(GTHREADS)
void gemm_hmma_kernel(const __nv_bfloat16* __restrict__ Ahi,
                      const __nv_bfloat16* __restrict__ Alo,
                      const __nv_bfloat16* __restrict__ Bhi,
                      const __nv_bfloat16* __restrict__ Blo,
                      float* __restrict__ C, int N, int K)
{
    extern __shared__ char smem[];
    const uint32_t sbase = smem_u32(smem);
    const int tid  = threadIdx.x;
    const int wid  = tid >> 5;
    const int lane = tid & 31;
    const int bm = blockIdx.y * BM;
    const int bn = blockIdx.x * BN;
    const int wm = (wid >> 2) * 64;     // warp m offset: 0 or 64
    const int wn = (wid & 3) * 64;      // warp n offset: 0..192

    const int NC = K / BKK;

    const int lrow = tid >> 2;          // 0..63
    const int lch  = tid & 3;
    auto load_stage = [&](int kc, int buf) {
        const uint32_t sb = sbase + buf * STAGE_BYTES;
        const int k0 = kc * BKK;
#pragma unroll
        for (int j = 0; j < 2; j++) {
            int r = lrow + j * 64;
            size_t go = (size_t)(bm + r) * K + k0 + lch * 8;
            uint32_t so = sb + r * ROWB + lch * 16;
            cp16(so,         Ahi + go);
            cp16(so + A_MAT, Alo + go);
        }
#pragma unroll
        for (int j = 0; j < 4; j++) {
            int r = lrow + j * 64;
            size_t go = (size_t)(bn + r) * K + k0 + lch * 8;
            uint32_t so = sb + B_OFF + r * ROWB + lch * 16;
            cp16(so,         Bhi + go);
            cp16(so + B_MAT, Blo + go);
        }
    };

    // ldmatrix lane addressing
    const int lr  = lane & 7;
    const int sel = lane >> 3;                     // 0..3
    const uint32_t a_lane_off = (uint32_t)((wm + lr + ((sel & 1) << 3)) * ROWB + ((sel >> 1) << 4));
    const uint32_t b_lane_off = (uint32_t)(B_OFF + (wn + lr + ((sel >> 1) << 3)) * ROWB + ((sel & 1) << 4));

    float acc[4][8][4];
#pragma unroll
    for (int mt = 0; mt < 4; mt++)
#pragma unroll
        for (int nt = 0; nt < 8; nt++)
#pragma unroll
            for (int r = 0; r < 4; r++) acc[mt][nt][r] = 0.f;

    load_stage(0, 0); CP_COMMIT();
    load_stage(1, 1); CP_COMMIT();

    int buf = 0;
    for (int it = 0; it < NC; it++) {
        if (it + 1 < NC) { CP_WAIT(1); } else { CP_WAIT(0); }
        __syncthreads();   // stage `it` visible to all; iter it-1 reads complete

        // prefetch stage it+2 into the buffer freed by iter it-1
        if (it + 2 < NC) { load_stage(it + 2, (buf + 2) % NSTAGE); CP_COMMIT(); }

        const uint32_t sb = sbase + buf * STAGE_BYTES;
#pragma unroll
        for (int ks = 0; ks < 2; ks++) {
            const uint32_t kofs = ks * 32;
            uint32_t ah[4][4], al[4][4];
#pragma unroll
            for (int mt = 0; mt < 4; mt++) {
                uint32_t addr = sb + a_lane_off + mt * (16 * ROWB) + kofs;
                ldsm4(ah[mt][0], ah[mt][1], ah[mt][2], ah[mt][3], addr);
                ldsm4(al[mt][0], al[mt][1], al[mt][2], al[mt][3], addr + A_MAT);
            }
#pragma unroll
            for (int ng = 0; ng < 4; ng++) {
                uint32_t bh[4], bl[4];
                uint32_t addr = sb + b_lane_off + ng * (16 * ROWB) + kofs;
                ldsm4(bh[0], bh[1], bh[2], bh[3], addr);
                ldsm4(bl[0], bl[1], bl[2], bl[3], addr + B_MAT);
#pragma unroll
                for (int mt = 0; mt < 4; mt++) {
#pragma unroll
                    for (int half = 0; half < 2; half++) {
                        float* a4 = acc[mt][ng * 2 + half];
                        uint32_t bh0 = bh[half*2], bh1 = bh[half*2+1];
                        uint32_t bl0 = bl[half*2], bl1 = bl[half*2+1];
                        mma16816(a4, ah[mt][0], ah[mt][1], ah[mt][2], ah[mt][3], bh0, bh1);
                        mma16816(a4, ah[mt][0], ah[mt][1], ah[mt][2], ah[mt][3], bl0, bl1);
                        mma16816(a4, al[mt][0], al[mt][1], al[mt][2], al[mt][3], bh0, bh1);
                    }
                }
            }
        }
        buf = (buf + 1) % NSTAGE;
    }

    // Epilogue: direct fp32 stores
    const int rrow = lane >> 2;
    const int rcol = (lane & 3) * 2;
#pragma unroll
    for (int mt = 0; mt < 4; mt++) {
        const int row0 = bm + wm + mt * 16 + rrow;
#pragma unroll
        for (int nt = 0; nt < 8; nt++) {
            const int col = bn + wn + nt * 8 + rcol;
            *(float2*)(C + (size_t)row0 * N + col)       = make_float2(acc[mt][nt][0], acc[mt][nt][1]);
            *(float2*)(C + (size_t)(row0 + 8) * N + col) = make_float2(acc[mt][nt][2], acc[mt][nt][3]);
        }
    }
}

// ---------------------------------------------------------------------------
// Conv + gates (per-head f/i split), channel-major outputs  [C, S]
// ---------------------------------------------------------------------------
__global__ __launch_bounds__(256)
void conv_gate_kernel(const float* __restrict__ cw)
{
    __shared__ float s_a[32][33];
    __shared__ float s_b[32][33];

    const int c  = blockIdx.x * 32 + threadIdx.x;
    const int fc = ((c >> 7) << 8) | (c & 127);
    const int ic = fc + 128;
    const int b  = blockIdx.z;
    const int t0 = blockIdx.y * 32;

    float wf[4], wi[4];
#pragma unroll
    for (int k = 0; k < 4; k++) { wf[k] = cw[fc * 4 + k]; wi[k] = cw[ic * 4 + k]; }

#pragma unroll
    for (int it = 0; it < 4; ++it) {
        const int tl = threadIdx.y + it * 8;
        const int t  = t0 + tl;
        const size_t rowbase = ((size_t)(b * SEQ + t)) * FOURH;
        float accf = 0.f, acci = 0.f;
#pragma unroll
        for (int k = 0; k < 4; k++) {
            int tp = t - 3 + k;
            if (tp >= 0) {
                size_t rb2 = ((size_t)(b * SEQ + tp)) * FOURH;
                accf = fmaf(wf[k], g_y[rb2 + 4096 + fc], accf);
                acci = fmaf(wi[k], g_y[rb2 + 4096 + ic], acci);
            }
        }
        const float h = g_y[rowbase + 2048 + c];
        const float f = 1.f / (1.f + __expf(-accf));
        const float i = 1.f / (1.f + __expf(-acci));
        const float denom = 1.f / (f + i + 1e-4f);
        s_a[tl][threadIdx.x] = f * denom;
        s_b[tl][threadIdx.x] = h * i * denom;
    }
    __syncthreads();

    const int lin = threadIdx.y * 32 + threadIdx.x;
    const int tw  = lin & 31;
    const int cb  = lin >> 5;
#pragma unroll
    for (int j = 0; j < 4; j++) {
        const int cl = cb + j * 8;
        const size_t idx = ((size_t)(b * HID + blockIdx.x * 32 + cl)) * SEQ + t0 + tw;
        g_a[idx] = s_a[tw][cl];
        g_b[idx] = s_b[tw][cl];
    }
}

// ---------------------------------------------------------------------------
// Linear scan per channel
// ---------------------------------------------------------------------------
__global__ __launch_bounds__(128)
void scan_kernel()
{
    const int ch  = blockIdx.x;
    const int tid = threadIdx.x;
    const size_t base = (size_t)ch * SEQ + (size_t)tid * 32;

    float a[32], bb[32];
#pragma unroll
    for (int j = 0; j < 32; j += 4) {
        float4 va = *(const float4*)(g_a + base + j);
        float4 vb = *(const float4*)(g_b + base + j);
        a[j+0]=va.x; a[j+1]=va.y; a[j+2]=va.z; a[j+3]=va.w;
        bb[j+0]=vb.x; bb[j+1]=vb.y; bb[j+2]=vb.z; bb[j+3]=vb.w;
    }

    float A = 1.f, Bv = 0.f;
#pragma unroll
    for (int j = 0; j < 32; j++) { Bv = fmaf(a[j], Bv, bb[j]); A *= a[j]; }

    __shared__ float sA[128], sB[128];
    sA[tid] = A; sB[tid] = Bv;
    __syncthreads();
    for (int off = 1; off < 128; off <<= 1) {
        float pA = 0.f, pB = 0.f;
        if (tid >= off) { pA = sA[tid - off]; pB = sB[tid - off]; }
        __syncthreads();
        if (tid >= off) { Bv = fmaf(A, pB, Bv); A = A * pA; sA[tid] = A; sB[tid] = Bv; }
        __syncthreads();
    }

    float h = (tid == 0) ? 0.f : sB[tid - 1];
#pragma unroll
    for (int j = 0; j < 32; j++) { h = fmaf(a[j], h, bb[j]); bb[j] = h; }
#pragma unroll
    for (int j = 0; j < 32; j += 4)
        *(float4*)(g_hs + base + j) = make_float4(bb[j], bb[j+1], bb[j+2], bb[j+3]);
}

// ---------------------------------------------------------------------------
// g = silu(out1) * out2 ; writes bf16 hi/lo for GEMM2
// ---------------------------------------------------------------------------
__global__ __launch_bounds__(256)
void silu_mul_kernel()
{
    __shared__ float sm[32][33];
    const int c0 = blockIdx.x * 32;
    const int s0 = blockIdx.y * 32;
    const int b  = blockIdx.z;

#pragma unroll
    for (int it = 0; it < 4; ++it) {
        const int cl = threadIdx.y + it * 8;
        const int s  = s0 + threadIdx.x;
        sm[cl][threadIdx.x] = g_hs[((size_t)(b * HID + c0 + cl)) * SEQ + s];
    }
    __syncthreads();

#pragma unroll
    for (int it = 0; it < 4; ++it) {
        const int sl = threadIdx.y + it * 8;
        const int s  = s0 + sl;
        const int c  = c0 + threadIdx.x;
        const size_t row = (size_t)(b * SEQ + s);
        const float o1 = g_y[row * FOURH + c];
        const float sil = o1 / (1.f + __expf(-o1));
        const float v = sil * sm[threadIdx.x][sl];
        __nv_bfloat16 h = __float2bfloat16_rn(v);
        g_ghi[row * HID + c] = h;
        g_glo[row * HID + c] = __float2bfloat16_rn(v - __bfloat162float(h));
    }
}

// ---------------------------------------------------------------------------
// Launch
// ---------------------------------------------------------------------------
extern "C" void kernel_launch(void* const* d_in, const int* in_sizes, int n_in,
                              void* d_out, int out_size)
{
    const float* x  = (const float*)d_in[0];
    const float* w1 = (const float*)d_in[1];
    const float* w2 = (const float*)d_in[2];
    const float* cw = (const float*)d_in[3];
    float* out = (float*)d_out;

    float *yp;
    cudaGetSymbolAddress((void**)&yp, g_y);
    __nv_bfloat16 *xhi, *xlo, *w1hi, *w1lo, *w2hi, *w2lo, *ghi, *glo;
    cudaGetSymbolAddress((void**)&xhi, g_xhi);
    cudaGetSymbolAddress((void**)&xlo, g_xlo);
    cudaGetSymbolAddress((void**)&w1hi, g_w1hi);
    cudaGetSymbolAddress((void**)&w1lo, g_w1lo);
    cudaGetSymbolAddress((void**)&w2hi, g_w2hi);
    cudaGetSymbolAddress((void**)&w2lo, g_w2lo);
    cudaGetSymbolAddress((void**)&ghi, g_ghi);
    cudaGetSymbolAddress((void**)&glo, g_glo);

    cudaFuncSetAttribute(gemm_hmma_kernel, cudaFuncAttributeMaxDynamicSharedMemorySize, SMEM_TOTAL_G);

    // splits
    {
        int n4 = MROWS * EMB / 4;
        split_kernel<<<(n4 + 255) / 256, 256>>>(x, xhi, xlo, n4);
        n4 = FOURH * EMB / 4;
        split_kernel<<<(n4 + 255) / 256, 256>>>(w1, w1hi, w1lo, n4);
        n4 = EMB * HID / 4;
        split_kernel<<<(n4 + 255) / 256, 256>>>(w2, w2hi, w2lo, n4);
    }

    // GEMM1: y[M,8192] = x @ w1^T
    gemm_hmma_kernel<<<dim3(FOURH / BN, MROWS / BM), GTHREADS, SMEM_TOTAL_G>>>(
        xhi, xlo, w1hi, w1lo, yp, FOURH, EMB);

    conv_gate_kernel<<<dim3(HID / 32, SEQ / 32, BSZ), dim3(32, 8)>>>(cw);
    scan_kernel<<<NCH, 128>>>();
    silu_mul_kernel<<<dim3(HID / 32, SEQ / 32, BSZ), dim3(32, 8)>>>();

    // GEMM2: out[M,1024] = g @ w2^T
    gemm_hmma_kernel<<<dim3(EMB / BN, MROWS / BM), GTHREADS, SMEM_TOTAL_G>>>(
        ghi, glo, w2hi, w2lo, out, EMB, HID);
}

// round 8
// speedup vs baseline: 3.5316x; 1.3354x over previous
#include <cuda_runtime.h>
#include <cuda_fp16.h>
#include <cuda_bf16.h>
#include <cstdint>

// ---------------------------------------------------------------------------
// Problem constants
// ---------------------------------------------------------------------------
#define BSZ      4
#define SEQ      4096
#define EMB      1024
#define HID      2048
#define FOURH    8192
#define MROWS    (BSZ*SEQ)      // 16384
#define NCH      (BSZ*HID)      // 8192 scan channels

// GEMM tile config (HMMA mma.sync — tcgen05 unavailable at .target sm_103)
#define BM 128
#define BN 256
#define BKK 32
#define ROWB 80                         // padded smem row stride (64B data + 16B pad)
#define A_MAT (128*ROWB)                // 10240
#define B_MAT (256*ROWB)                // 20480
#define B_OFF (2*A_MAT)                 // Ahi | Alo | B
#define STAGE_BYTES (2*A_MAT + B_MAT)   // 40960
#define NSTAGE 3
#define SMEM_TOTAL_G (NSTAGE*STAGE_BYTES)   // 122880
#define GTHREADS 256

// ---------------------------------------------------------------------------
// Scratch (static device globals)
// ---------------------------------------------------------------------------
__device__ float g_y [(size_t)MROWS * FOURH];
__device__ float g_a [(size_t)NCH   * SEQ];
__device__ float g_b [(size_t)NCH   * SEQ];
__device__ float g_hs[(size_t)NCH   * SEQ];
__device__ __half g_xhi[(size_t)MROWS * EMB];
__device__ __half g_xlo[(size_t)MROWS * EMB];
__device__ __half g_w1h[(size_t)FOURH * EMB];
__device__ __half g_w2h[(size_t)EMB * HID];
__device__ __half g_ghi[(size_t)MROWS * HID];
__device__ __half g_glo[(size_t)MROWS * HID];

// ---------------------------------------------------------------------------
// PTX helpers (sm_80-baseline)
// ---------------------------------------------------------------------------
__device__ __forceinline__ uint32_t smem_u32(const void* p) {
    uint32_t a;
    asm("{ .reg .u64 t; cvta.to.shared.u64 t, %1; cvt.u32.u64 %0, t; }" : "=r"(a) : "l"(p));
    return a;
}
__device__ __forceinline__ void cp16(uint32_t s, const void* g) {
    asm volatile("cp.async.cg.shared.global [%0], [%1], 16;" :: "r"(s), "l"(g));
}
#define CP_COMMIT() asm volatile("cp.async.commit_group;" ::: "memory")
#define CP_WAIT(n)  asm volatile("cp.async.wait_group %0;" :: "n"(n) : "memory")

__device__ __forceinline__ void ldsm4(uint32_t& r0, uint32_t& r1, uint32_t& r2, uint32_t& r3,
                                      uint32_t addr) {
    asm volatile("ldmatrix.sync.aligned.m8n8.x4.shared.b16 {%0,%1,%2,%3}, [%4];"
                 : "=r"(r0), "=r"(r1), "=r"(r2), "=r"(r3) : "r"(addr));
}
__device__ __forceinline__ void mma16816(float* c, uint32_t a0, uint32_t a1, uint32_t a2,
                                         uint32_t a3, uint32_t b0, uint32_t b1) {
    asm volatile(
        "mma.sync.aligned.m16n8k16.row.col.f32.f16.f16.f32 "
        "{%0,%1,%2,%3}, {%4,%5,%6,%7}, {%8,%9}, {%0,%1,%2,%3};"
        : "+f"(c[0]), "+f"(c[1]), "+f"(c[2]), "+f"(c[3])
        : "r"(a0), "r"(a1), "r"(a2), "r"(a3), "r"(b0), "r"(b1));
}

// ---------------------------------------------------------------------------
// fp32 -> fp16 hi/lo split (A-side operands)
// ---------------------------------------------------------------------------
__global__ __launch_bounds__(256)
void split2_kernel(const float* __restrict__ in,
                   __half* __restrict__ hi,
                   __half* __restrict__ lo, int n4)
{
    int i = blockIdx.x * 256 + threadIdx.x;
    if (i >= n4) return;
    float4 v = ((const float4*)in)[i];
    __half h0 = __float2half_rn(v.x);
    __half h1 = __float2half_rn(v.y);
    __half h2 = __float2half_rn(v.z);
    __half h3 = __float2half_rn(v.w);
    __half2* hp = (__half2*)hi;
    __half2* lp = (__half2*)lo;
    hp[2*i]   = __half2(h0, h1);
    hp[2*i+1] = __half2(h2, h3);
    lp[2*i]   = __half2(__float2half_rn(v.x - __half2float(h0)),
                        __float2half_rn(v.y - __half2float(h1)));
    lp[2*i+1] = __half2(__float2half_rn(v.z - __half2float(h2)),
                        __float2half_rn(v.w - __half2float(h3)));
}

// fp32 -> fp16 round (B-side operands = weights)
__global__ __launch_bounds__(256)
void round1_kernel(const float* __restrict__ in, __half* __restrict__ out, int n4)
{
    int i = blockIdx.x * 256 + threadIdx.x;
    if (i >= n4) return;
    float4 v = ((const float4*)in)[i];
    __half2* op = (__half2*)out;
    op[2*i]   = __half2(__float2half_rn(v.x), __float2half_rn(v.y));
    op[2*i+1] = __half2(__float2half_rn(v.z), __float2half_rn(v.w));
}

// ---------------------------------------------------------------------------
// HMMA fp16 split-A GEMM: C[M,N] = A[M,K] @ B[N,K]^T  (~22-bit A, 11-bit B)
// CTA tile 128x256, BK=32, 3-stage cp.async pipeline (1 sync/iter),
// 256 threads, warp grid 2(M)x4(N), warp tile 64x64, 2 MMAs per fragment.
// ---------------------------------------------------------------------------
__global__ __launch_bounds__(GTHREADS)
void gemm_hmma_kernel(const __half* __restrict__ Ahi,
                      const __half* __restrict__ Alo,
                      const __half* __restrict__ Bh,
                      float* __restrict__ C, int N, int K)
{
    extern __shared__ char smem[];
    const uint32_t sbase = smem_u32(smem);
    const int tid  = threadIdx.x;
    const int wid  = tid >> 5;
    const int lane = tid & 31;
    const int bm = blockIdx.y * BM;
    const int bn = blockIdx.x * BN;
    const int wm = (wid >> 2) * 64;
    const int wn = (wid & 3) * 64;

    const int NC = K / BKK;

    const int lrow = tid >> 2;          // 0..63
    const int lch  = tid & 3;
    auto load_stage = [&](int kc, int buf) {
        const uint32_t sb = sbase + buf * STAGE_BYTES;
        const int k0 = kc * BKK;
#pragma unroll
        for (int j = 0; j < 2; j++) {
            int r = lrow + j * 64;
            size_t go = (size_t)(bm + r) * K + k0 + lch * 8;
            uint32_t so = sb + r * ROWB + lch * 16;
            cp16(so,         Ahi + go);
            cp16(so + A_MAT, Alo + go);
        }
#pragma unroll
        for (int j = 0; j < 4; j++) {
            int r = lrow + j * 64;
            size_t go = (size_t)(bn + r) * K + k0 + lch * 8;
            uint32_t so = sb + B_OFF + r * ROWB + lch * 16;
            cp16(so, Bh + go);
        }
    };

    // ldmatrix lane addressing
    const int lr  = lane & 7;
    const int sel = lane >> 3;
    const uint32_t a_lane_off = (uint32_t)((wm + lr + ((sel & 1) << 3)) * ROWB + ((sel >> 1) << 4));
    const uint32_t b_lane_off = (uint32_t)(B_OFF + (wn + lr + ((sel >> 1) << 3)) * ROWB + ((sel & 1) << 4));

    float acc[4][8][4];
#pragma unroll
    for (int mt = 0; mt < 4; mt++)
#pragma unroll
        for (int nt = 0; nt < 8; nt++)
#pragma unroll
            for (int r = 0; r < 4; r++) acc[mt][nt][r] = 0.f;

    load_stage(0, 0); CP_COMMIT();
    load_stage(1, 1); CP_COMMIT();

    int buf = 0;
    for (int it = 0; it < NC; it++) {
        if (it + 1 < NC) { CP_WAIT(1); } else { CP_WAIT(0); }
        __syncthreads();

        if (it + 2 < NC) { load_stage(it + 2, (buf + 2) % NSTAGE); CP_COMMIT(); }

        const uint32_t sb = sbase + buf * STAGE_BYTES;
#pragma unroll
        for (int ks = 0; ks < 2; ks++) {
            const uint32_t kofs = ks * 32;
            uint32_t ah[4][4], al[4][4];
#pragma unroll
            for (int mt = 0; mt < 4; mt++) {
                uint32_t addr = sb + a_lane_off + mt * (16 * ROWB) + kofs;
                ldsm4(ah[mt][0], ah[mt][1], ah[mt][2], ah[mt][3], addr);
                ldsm4(al[mt][0], al[mt][1], al[mt][2], al[mt][3], addr + A_MAT);
            }
#pragma unroll
            for (int ng = 0; ng < 4; ng++) {
                uint32_t bh[4];
                uint32_t addr = sb + b_lane_off + ng * (16 * ROWB) + kofs;
                ldsm4(bh[0], bh[1], bh[2], bh[3], addr);
#pragma unroll
                for (int mt = 0; mt < 4; mt++) {
#pragma unroll
                    for (int half = 0; half < 2; half++) {
                        float* a4 = acc[mt][ng * 2 + half];
                        uint32_t b0 = bh[half*2], b1 = bh[half*2+1];
                        mma16816(a4, ah[mt][0], ah[mt][1], ah[mt][2], ah[mt][3], b0, b1);
                        mma16816(a4, al[mt][0], al[mt][1], al[mt][2], al[mt][3], b0, b1);
                    }
                }
            }
        }
        buf = (buf + 1) % NSTAGE;
    }

    // Epilogue: direct fp32 stores
    const int rrow = lane >> 2;
    const int rcol = (lane & 3) * 2;
#pragma unroll
    for (int mt = 0; mt < 4; mt++) {
        const int row0 = bm + wm + mt * 16 + rrow;
#pragma unroll
        for (int nt = 0; nt < 8; nt++) {
            const int col = bn + wn + nt * 8 + rcol;
            *(float2*)(C + (size_t)row0 * N + col)       = make_float2(acc[mt][nt][0], acc[mt][nt][1]);
            *(float2*)(C + (size_t)(row0 + 8) * N + col) = make_float2(acc[mt][nt][2], acc[mt][nt][3]);
        }
    }
}

// ---------------------------------------------------------------------------
// Conv + gates (per-head f/i split), channel-major outputs  [C, S]
// ---------------------------------------------------------------------------
__global__ __launch_bounds__(256)
void conv_gate_kernel(const float* __restrict__ cw)
{
    __shared__ float s_a[32][33];
    __shared__ float s_b[32][33];

    const int c  = blockIdx.x * 32 + threadIdx.x;
    const int fc = ((c >> 7) << 8) | (c & 127);
    const int ic = fc + 128;
    const int b  = blockIdx.z;
    const int t0 = blockIdx.y * 32;

    float wf[4], wi[4];
#pragma unroll
    for (int k = 0; k < 4; k++) { wf[k] = cw[fc * 4 + k]; wi[k] = cw[ic * 4 + k]; }

#pragma unroll
    for (int it = 0; it < 4; ++it) {
        const int tl = threadIdx.y + it * 8;
        const int t  = t0 + tl;
        const size_t rowbase = ((size_t)(b * SEQ + t)) * FOURH;
        float accf = 0.f, acci = 0.f;
#pragma unroll
        for (int k = 0; k < 4; k++) {
            int tp = t - 3 + k;
            if (tp >= 0) {
                size_t rb2 = ((size_t)(b * SEQ + tp)) * FOURH;
                accf = fmaf(wf[k], g_y[rb2 + 4096 + fc], accf);
                acci = fmaf(wi[k], g_y[rb2 + 4096 + ic], acci);
            }
        }
        const float h = g_y[rowbase + 2048 + c];
        const float f = 1.f / (1.f + __expf(-accf));
        const float i = 1.f / (1.f + __expf(-acci));
        const float denom = 1.f / (f + i + 1e-4f);
        s_a[tl][threadIdx.x] = f * denom;
        s_b[tl][threadIdx.x] = h * i * denom;
    }
    __syncthreads();

    const int lin = threadIdx.y * 32 + threadIdx.x;
    const int tw  = lin & 31;
    const int cb  = lin >> 5;
#pragma unroll
    for (int j = 0; j < 4; j++) {
        const int cl = cb + j * 8;
        const size_t idx = ((size_t)(b * HID + blockIdx.x * 32 + cl)) * SEQ + t0 + tw;
        g_a[idx] = s_a[tw][cl];
        g_b[idx] = s_b[tw][cl];
    }
}

// ---------------------------------------------------------------------------
// Linear scan per channel
// ---------------------------------------------------------------------------
__global__ __launch_bounds__(128)
void scan_kernel()
{
    const int ch  = blockIdx.x;
    const int tid = threadIdx.x;
    const size_t base = (size_t)ch * SEQ + (size_t)tid * 32;

    float a[32], bb[32];
#pragma unroll
    for (int j = 0; j < 32; j += 4) {
        float4 va = *(const float4*)(g_a + base + j);
        float4 vb = *(const float4*)(g_b + base + j);
        a[j+0]=va.x; a[j+1]=va.y; a[j+2]=va.z; a[j+3]=va.w;
        bb[j+0]=vb.x; bb[j+1]=vb.y; bb[j+2]=vb.z; bb[j+3]=vb.w;
    }

    float A = 1.f, Bv = 0.f;
#pragma unroll
    for (int j = 0; j < 32; j++) { Bv = fmaf(a[j], Bv, bb[j]); A *= a[j]; }

    __shared__ float sA[128], sB[128];
    sA[tid] = A; sB[tid] = Bv;
    __syncthreads();
    for (int off = 1; off < 128; off <<= 1) {
        float pA = 0.f, pB = 0.f;
        if (tid >= off) { pA = sA[tid - off]; pB = sB[tid - off]; }
        __syncthreads();
        if (tid >= off) { Bv = fmaf(A, pB, Bv); A = A * pA; sA[tid] = A; sB[tid] = Bv; }
        __syncthreads();
    }

    float h = (tid == 0) ? 0.f : sB[tid - 1];
#pragma unroll
    for (int j = 0; j < 32; j++) { h = fmaf(a[j], h, bb[j]); bb[j] = h; }
#pragma unroll
    for (int j = 0; j < 32; j += 4)
        *(float4*)(g_hs + base + j) = make_float4(bb[j], bb[j+1], bb[j+2], bb[j+3]);
}

// ---------------------------------------------------------------------------
// g = silu(out1) * out2 ; writes fp16 hi/lo for GEMM2
// ---------------------------------------------------------------------------
__global__ __launch_bounds__(256)
void silu_mul_kernel()
{
    __shared__ float sm[32][33];
    const int c0 = blockIdx.x * 32;
    const int s0 = blockIdx.y * 32;
    const int b  = blockIdx.z;

#pragma unroll
    for (int it = 0; it < 4; ++it) {
        const int cl = threadIdx.y + it * 8;
        const int s  = s0 + threadIdx.x;
        sm[cl][threadIdx.x] = g_hs[((size_t)(b * HID + c0 + cl)) * SEQ + s];
    }
    __syncthreads();

#pragma unroll
    for (int it = 0; it < 4; ++it) {
        const int sl = threadIdx.y + it * 8;
        const int s  = s0 + sl;
        const int c  = c0 + threadIdx.x;
        const size_t row = (size_t)(b * SEQ + s);
        const float o1 = g_y[row * FOURH + c];
        const float sil = o1 / (1.f + __expf(-o1));
        const float v = sil * sm[threadIdx.x][sl];
        __half h = __float2half_rn(v);
        g_ghi[row * HID + c] = h;
        g_glo[row * HID + c] = __float2half_rn(v - __half2float(h));
    }
}

// ---------------------------------------------------------------------------
// Launch
// ---------------------------------------------------------------------------
extern "C" void kernel_launch(void* const* d_in, const int* in_sizes, int n_in,
                              void* d_out, int out_size)
{
    const float* x  = (const float*)d_in[0];
    const float* w1 = (const float*)d_in[1];
    const float* w2 = (const float*)d_in[2];
    const float* cw = (const float*)d_in[3];
    float* out = (float*)d_out;

    float *yp;
    cudaGetSymbolAddress((void**)&yp, g_y);
    __half *xhi, *xlo, *w1h, *w2h, *ghi, *glo;
    cudaGetSymbolAddress((void**)&xhi, g_xhi);
    cudaGetSymbolAddress((void**)&xlo, g_xlo);
    cudaGetSymbolAddress((void**)&w1h, g_w1h);
    cudaGetSymbolAddress((void**)&w2h, g_w2h);
    cudaGetSymbolAddress((void**)&ghi, g_ghi);
    cudaGetSymbolAddress((void**)&glo, g_glo);

    cudaFuncSetAttribute(gemm_hmma_kernel, cudaFuncAttributeMaxDynamicSharedMemorySize, SMEM_TOTAL_G);

    // conversions
    {
        int n4 = MROWS * EMB / 4;
        split2_kernel<<<(n4 + 255) / 256, 256>>>(x, xhi, xlo, n4);
        n4 = FOURH * EMB / 4;
        round1_kernel<<<(n4 + 255) / 256, 256>>>(w1, w1h, n4);
        n4 = EMB * HID / 4;
        round1_kernel<<<(n4 + 255) / 256, 256>>>(w2, w2h, n4);
    }

    // GEMM1: y[M,8192] = x @ w1^T
    gemm_hmma_kernel<<<dim3(FOURH / BN, MROWS / BM), GTHREADS, SMEM_TOTAL_G>>>(
        xhi, xlo, w1h, yp, FOURH, EMB);

    conv_gate_kernel<<<dim3(HID / 32, SEQ / 32, BSZ), dim3(32, 8)>>>(cw);
    scan_kernel<<<NCH, 128>>>();
    silu_mul_kernel<<<dim3(HID / 32, SEQ / 32, BSZ), dim3(32, 8)>>>();

    // GEMM2: out[M,1024] = g @ w2^T
    gemm_hmma_kernel<<<dim3(EMB / BN, MROWS / BM), GTHREADS, SMEM_TOTAL_G>>>(
        ghi, glo, w2h, out, EMB, HID);
}

// round 9
// speedup vs baseline: 4.6151x; 1.3068x over previous
#include <cuda_runtime.h>
#include <cuda_fp16.h>
#include <cstdint>

// ---------------------------------------------------------------------------
// Problem constants
// ---------------------------------------------------------------------------
#define BSZ      4
#define SEQ      4096
#define EMB      1024
#define HID      2048
#define FOURH    8192
#define MROWS    (BSZ*SEQ)      // 16384
#define NCH      (BSZ*HID)      // 8192 scan channels

// GEMM tile config (HMMA mma.sync — tcgen05 unavailable at .target sm_103)
#define BM 128
#define BN 256
#define BKK 32
#define ROWB 80                         // padded smem row stride (64B data + 16B pad)
#define A_MAT (128*ROWB)                // 10240
#define B_MAT (256*ROWB)                // 20480
#define NSTAGE 3
#define GTHREADS 256

// ---------------------------------------------------------------------------
// Scratch (static device globals)
// ---------------------------------------------------------------------------
__device__ float g_y [(size_t)MROWS * FOURH];
__device__ float g_a [(size_t)NCH   * SEQ];
__device__ float g_b [(size_t)NCH   * SEQ];
__device__ float g_hs[(size_t)NCH   * SEQ];
__device__ __half g_xh [(size_t)MROWS * EMB];
__device__ __half g_w1h[(size_t)FOURH * EMB];
__device__ __half g_w2h[(size_t)EMB * HID];
__device__ __half g_ghi[(size_t)MROWS * HID];
__device__ __half g_glo[(size_t)MROWS * HID];

// ---------------------------------------------------------------------------
// PTX helpers (sm_80-baseline)
// ---------------------------------------------------------------------------
__device__ __forceinline__ uint32_t smem_u32(const void* p) {
    uint32_t a;
    asm("{ .reg .u64 t; cvta.to.shared.u64 t, %1; cvt.u32.u64 %0, t; }" : "=r"(a) : "l"(p));
    return a;
}
__device__ __forceinline__ void cp16(uint32_t s, const void* g) {
    asm volatile("cp.async.cg.shared.global [%0], [%1], 16;" :: "r"(s), "l"(g));
}
#define CP_COMMIT() asm volatile("cp.async.commit_group;" ::: "memory")
#define CP_WAIT(n)  asm volatile("cp.async.wait_group %0;" :: "n"(n) : "memory")

__device__ __forceinline__ void ldsm4(uint32_t& r0, uint32_t& r1, uint32_t& r2, uint32_t& r3,
                                      uint32_t addr) {
    asm volatile("ldmatrix.sync.aligned.m8n8.x4.shared.b16 {%0,%1,%2,%3}, [%4];"
                 : "=r"(r0), "=r"(r1), "=r"(r2), "=r"(r3) : "r"(addr));
}
__device__ __forceinline__ void mma16816(float* c, uint32_t a0, uint32_t a1, uint32_t a2,
                                         uint32_t a3, uint32_t b0, uint32_t b1) {
    asm volatile(
        "mma.sync.aligned.m16n8k16.row.col.f32.f16.f16.f32 "
        "{%0,%1,%2,%3}, {%4,%5,%6,%7}, {%8,%9}, {%0,%1,%2,%3};"
        : "+f"(c[0]), "+f"(c[1]), "+f"(c[2]), "+f"(c[3])
        : "r"(a0), "r"(a1), "r"(a2), "r"(a3), "r"(b0), "r"(b1));
}

// ---------------------------------------------------------------------------
// Conversions
// ---------------------------------------------------------------------------
__global__ __launch_bounds__(256)
void round1_kernel(const float* __restrict__ in, __half* __restrict__ out, int n4)
{
    int i = blockIdx.x * 256 + threadIdx.x;
    if (i >= n4) return;
    float4 v = ((const float4*)in)[i];
    __half2* op = (__half2*)out;
    op[2*i]   = __half2(__float2half_rn(v.x), __float2half_rn(v.y));
    op[2*i+1] = __half2(__float2half_rn(v.z), __float2half_rn(v.w));
}

// ---------------------------------------------------------------------------
// HMMA fp16 GEMM: C[M,N] = A[M,K] @ B[N,K]^T.
// SPLIT=1: A provided as hi+lo fp16 pair (2 MMA passes, ~22-bit A).
// SPLIT=0: single fp16 A (1 pass).
// CTA tile 128x256, BK=32, 3-stage cp.async pipeline (1 sync/iter),
// 256 threads, warp grid 2(M)x4(N), warp tile 64x64.
// ---------------------------------------------------------------------------
template <int SPLIT>
__global__ __launch_bounds__(GTHREADS)
void gemm_hmma_kernel(const __half* __restrict__ Ahi,
                      const __half* __restrict__ Alo,
                      const __half* __restrict__ Bh,
                      float* __restrict__ C, int N, int K)
{
    constexpr uint32_t B_OFFC = (SPLIT ? 2 : 1) * A_MAT;
    constexpr uint32_t STAGE  = B_OFFC + B_MAT;

    extern __shared__ char smem[];
    const uint32_t sbase = smem_u32(smem);
    const int tid  = threadIdx.x;
    const int wid  = tid >> 5;
    const int lane = tid & 31;
    const int bm = blockIdx.y * BM;
    const int bn = blockIdx.x * BN;
    const int wm = (wid >> 2) * 64;
    const int wn = (wid & 3) * 64;

    const int NC = K / BKK;

    const int lrow = tid >> 2;          // 0..63
    const int lch  = tid & 3;
    auto load_stage = [&](int kc, int buf) {
        const uint32_t sb = sbase + buf * STAGE;
        const int k0 = kc * BKK;
#pragma unroll
        for (int j = 0; j < 2; j++) {
            int r = lrow + j * 64;
            size_t go = (size_t)(bm + r) * K + k0 + lch * 8;
            uint32_t so = sb + r * ROWB + lch * 16;
            cp16(so, Ahi + go);
            if (SPLIT) cp16(so + A_MAT, Alo + go);
        }
#pragma unroll
        for (int j = 0; j < 4; j++) {
            int r = lrow + j * 64;
            size_t go = (size_t)(bn + r) * K + k0 + lch * 8;
            uint32_t so = sb + B_OFFC + r * ROWB + lch * 16;
            cp16(so, Bh + go);
        }
    };

    // ldmatrix lane addressing
    const int lr  = lane & 7;
    const int sel = lane >> 3;
    const uint32_t a_lane_off = (uint32_t)((wm + lr + ((sel & 1) << 3)) * ROWB + ((sel >> 1) << 4));
    const uint32_t b_lane_off = (uint32_t)(B_OFFC + (wn + lr + ((sel >> 1) << 3)) * ROWB + ((sel & 1) << 4));

    float acc[4][8][4];
#pragma unroll
    for (int mt = 0; mt < 4; mt++)
#pragma unroll
        for (int nt = 0; nt < 8; nt++)
#pragma unroll
            for (int r = 0; r < 4; r++) acc[mt][nt][r] = 0.f;

    load_stage(0, 0); CP_COMMIT();
    load_stage(1, 1); CP_COMMIT();

    int buf = 0;
    for (int it = 0; it < NC; it++) {
        if (it + 1 < NC) { CP_WAIT(1); } else { CP_WAIT(0); }
        __syncthreads();

        if (it + 2 < NC) { load_stage(it + 2, (buf + 2) % NSTAGE); CP_COMMIT(); }

        const uint32_t sb = sbase + buf * STAGE;
#pragma unroll
        for (int ks = 0; ks < 2; ks++) {
            const uint32_t kofs = ks * 32;
            uint32_t ah[4][4], al[4][4];
#pragma unroll
            for (int mt = 0; mt < 4; mt++) {
                uint32_t addr = sb + a_lane_off + mt * (16 * ROWB) + kofs;
                ldsm4(ah[mt][0], ah[mt][1], ah[mt][2], ah[mt][3], addr);
                if (SPLIT) ldsm4(al[mt][0], al[mt][1], al[mt][2], al[mt][3], addr + A_MAT);
            }
#pragma unroll
            for (int ng = 0; ng < 4; ng++) {
                uint32_t bh[4];
                uint32_t addr = sb + b_lane_off + ng * (16 * ROWB) + kofs;
                ldsm4(bh[0], bh[1], bh[2], bh[3], addr);
#pragma unroll
                for (int mt = 0; mt < 4; mt++) {
#pragma unroll
                    for (int half = 0; half < 2; half++) {
                        float* a4 = acc[mt][ng * 2 + half];
                        uint32_t b0 = bh[half*2], b1 = bh[half*2+1];
                        mma16816(a4, ah[mt][0], ah[mt][1], ah[mt][2], ah[mt][3], b0, b1);
                        if (SPLIT)
                            mma16816(a4, al[mt][0], al[mt][1], al[mt][2], al[mt][3], b0, b1);
                    }
                }
            }
        }
        buf = (buf + 1) % NSTAGE;
    }

    // Epilogue: direct fp32 stores
    const int rrow = lane >> 2;
    const int rcol = (lane & 3) * 2;
#pragma unroll
    for (int mt = 0; mt < 4; mt++) {
        const int row0 = bm + wm + mt * 16 + rrow;
#pragma unroll
        for (int nt = 0; nt < 8; nt++) {
            const int col = bn + wn + nt * 8 + rcol;
            *(float2*)(C + (size_t)row0 * N + col)       = make_float2(acc[mt][nt][0], acc[mt][nt][1]);
            *(float2*)(C + (size_t)(row0 + 8) * N + col) = make_float2(acc[mt][nt][2], acc[mt][nt][3]);
        }
    }
}

// ---------------------------------------------------------------------------
// Conv + gates (per-head f/i split), channel-major outputs  [C, S]
// ---------------------------------------------------------------------------
__global__ __launch_bounds__(256)
void conv_gate_kernel(const float* __restrict__ cw)
{
    __shared__ float s_a[32][33];
    __shared__ float s_b[32][33];

    const int c  = blockIdx.x * 32 + threadIdx.x;
    const int fc = ((c >> 7) << 8) | (c & 127);
    const int ic = fc + 128;
    const int b  = blockIdx.z;
    const int t0 = blockIdx.y * 32;

    float wf[4], wi[4];
#pragma unroll
    for (int k = 0; k < 4; k++) { wf[k] = cw[fc * 4 + k]; wi[k] = cw[ic * 4 + k]; }

#pragma unroll
    for (int it = 0; it < 4; ++it) {
        const int tl = threadIdx.y + it * 8;
        const int t  = t0 + tl;
        const size_t rowbase = ((size_t)(b * SEQ + t)) * FOURH;
        float accf = 0.f, acci = 0.f;
#pragma unroll
        for (int k = 0; k < 4; k++) {
            int tp = t - 3 + k;
            if (tp >= 0) {
                size_t rb2 = ((size_t)(b * SEQ + tp)) * FOURH;
                accf = fmaf(wf[k], g_y[rb2 + 4096 + fc], accf);
                acci = fmaf(wi[k], g_y[rb2 + 4096 + ic], acci);
            }
        }
        const float h = g_y[rowbase + 2048 + c];
        const float f = 1.f / (1.f + __expf(-accf));
        const float i = 1.f / (1.f + __expf(-acci));
        const float denom = 1.f / (f + i + 1e-4f);
        s_a[tl][threadIdx.x] = f * denom;
        s_b[tl][threadIdx.x] = h * i * denom;
    }
    __syncthreads();

    const int lin = threadIdx.y * 32 + threadIdx.x;
    const int tw  = lin & 31;
    const int cb  = lin >> 5;
#pragma unroll
    for (int j = 0; j < 4; j++) {
        const int cl = cb + j * 8;
        const size_t idx = ((size_t)(b * HID + blockIdx.x * 32 + cl)) * SEQ + t0 + tw;
        g_a[idx] = s_a[tw][cl];
        g_b[idx] = s_b[tw][cl];
    }
}

// ---------------------------------------------------------------------------
// Linear scan per channel
// ---------------------------------------------------------------------------
__global__ __launch_bounds__(128)
void scan_kernel()
{
    const int ch  = blockIdx.x;
    const int tid = threadIdx.x;
    const size_t base = (size_t)ch * SEQ + (size_t)tid * 32;

    float a[32], bb[32];
#pragma unroll
    for (int j = 0; j < 32; j += 4) {
        float4 va = *(const float4*)(g_a + base + j);
        float4 vb = *(const float4*)(g_b + base + j);
        a[j+0]=va.x; a[j+1]=va.y; a[j+2]=va.z; a[j+3]=va.w;
        bb[j+0]=vb.x; bb[j+1]=vb.y; bb[j+2]=vb.z; bb[j+3]=vb.w;
    }

    float A = 1.f, Bv = 0.f;
#pragma unroll
    for (int j = 0; j < 32; j++) { Bv = fmaf(a[j], Bv, bb[j]); A *= a[j]; }

    __shared__ float sA[128], sB[128];
    sA[tid] = A; sB[tid] = Bv;
    __syncthreads();
    for (int off = 1; off < 128; off <<= 1) {
        float pA = 0.f, pB = 0.f;
        if (tid >= off) { pA = sA[tid - off]; pB = sB[tid - off]; }
        __syncthreads();
        if (tid >= off) { Bv = fmaf(A, pB, Bv); A = A * pA; sA[tid] = A; sB[tid] = Bv; }
        __syncthreads();
    }

    float h = (tid == 0) ? 0.f : sB[tid - 1];
#pragma unroll
    for (int j = 0; j < 32; j++) { h = fmaf(a[j], h, bb[j]); bb[j] = h; }
#pragma unroll
    for (int j = 0; j < 32; j += 4)
        *(float4*)(g_hs + base + j) = make_float4(bb[j], bb[j+1], bb[j+2], bb[j+3]);
}

// ---------------------------------------------------------------------------
// g = silu(out1) * out2 ; writes fp16 hi/lo for GEMM2
// ---------------------------------------------------------------------------
__global__ __launch_bounds__(256)
void silu_mul_kernel()
{
    __shared__ float sm[32][33];
    const int c0 = blockIdx.x * 32;
    const int s0 = blockIdx.y * 32;
    const int b  = blockIdx.z;

#pragma unroll
    for (int it = 0; it < 4; ++it) {
        const int cl = threadIdx.y + it * 8;
        const int s  = s0 + threadIdx.x;
        sm[cl][threadIdx.x] = g_hs[((size_t)(b * HID + c0 + cl)) * SEQ + s];
    }
    __syncthreads();

#pragma unroll
    for (int it = 0; it < 4; ++it) {
        const int sl = threadIdx.y + it * 8;
        const int s  = s0 + sl;
        const int c  = c0 + threadIdx.x;
        const size_t row = (size_t)(b * SEQ + s);
        const float o1 = g_y[row * FOURH + c];
        const float sil = o1 / (1.f + __expf(-o1));
        const float v = sil * sm[threadIdx.x][sl];
        __half h = __float2half_rn(v);
        g_ghi[row * HID + c] = h;
        g_glo[row * HID + c] = __float2half_rn(v - __half2float(h));
    }
}

// ---------------------------------------------------------------------------
// Launch
// ---------------------------------------------------------------------------
extern "C" void kernel_launch(void* const* d_in, const int* in_sizes, int n_in,
                              void* d_out, int out_size)
{
    const float* x  = (const float*)d_in[0];
    const float* w1 = (const float*)d_in[1];
    const float* w2 = (const float*)d_in[2];
    const float* cw = (const float*)d_in[3];
    float* out = (float*)d_out;

    float *yp;
    cudaGetSymbolAddress((void**)&yp, g_y);
    __half *xh, *w1h, *w2h, *ghi, *glo;
    cudaGetSymbolAddress((void**)&xh,  g_xh);
    cudaGetSymbolAddress((void**)&w1h, g_w1h);
    cudaGetSymbolAddress((void**)&w2h, g_w2h);
    cudaGetSymbolAddress((void**)&ghi, g_ghi);
    cudaGetSymbolAddress((void**)&glo, g_glo);

    const int smem1 = NSTAGE * (A_MAT + B_MAT);        // single-A stage
    const int smem2 = NSTAGE * (2 * A_MAT + B_MAT);    // split-A stage
    cudaFuncSetAttribute(gemm_hmma_kernel<0>, cudaFuncAttributeMaxDynamicSharedMemorySize, smem1);
    cudaFuncSetAttribute(gemm_hmma_kernel<1>, cudaFuncAttributeMaxDynamicSharedMemorySize, smem2);

    // conversions
    {
        int n4 = MROWS * EMB / 4;
        round1_kernel<<<(n4 + 255) / 256, 256>>>(x, xh, n4);
        n4 = FOURH * EMB / 4;
        round1_kernel<<<(n4 + 255) / 256, 256>>>(w1, w1h, n4);
        n4 = EMB * HID / 4;
        round1_kernel<<<(n4 + 255) / 256, 256>>>(w2, w2h, n4);
    }

    // GEMM1 (single fp16 A): y[M,8192] = x @ w1^T
    gemm_hmma_kernel<0><<<dim3(FOURH / BN, MROWS / BM), GTHREADS, smem1>>>(
        xh, nullptr, w1h, yp, FOURH, EMB);

    conv_gate_kernel<<<dim3(HID / 32, SEQ / 32, BSZ), dim3(32, 8)>>>(cw);
    scan_kernel<<<NCH, 128>>>();
    silu_mul_kernel<<<dim3(HID / 32, SEQ / 32, BSZ), dim3(32, 8)>>>();

    // GEMM2 (split-A, ~22-bit): out[M,1024] = g @ w2^T
    gemm_hmma_kernel<1><<<dim3(EMB / BN, MROWS / BM), GTHREADS, smem2>>>(
        ghi, glo, w2h, out, EMB, HID);
}

// round 10
// speedup vs baseline: 5.7510x; 1.2461x over previous
#include <cuda_runtime.h>
#include <cuda_fp16.h>
#include <cstdint>

// ---------------------------------------------------------------------------
// Problem constants
// ---------------------------------------------------------------------------
#define BSZ      4
#define SEQ      4096
#define EMB      1024
#define HID      2048
#define FOURH    8192
#define MROWS    (BSZ*SEQ)      // 16384
#define NCH      (BSZ*HID)      // 8192 scan channels

// GEMM tile config (HMMA mma.sync — tcgen05 unavailable at .target sm_103)
#define BM 128
#define BN 128
#define BKK 32
#define ROWB 80                         // padded smem row stride (64B data + 16B pad)
#define A_MAT (128*ROWB)                // 10240
#define B_MATN (128*ROWB)               // 10240
#define NSTAGE 3
#define GTHREADS 256

// ---------------------------------------------------------------------------
// Scratch (static device globals)
// ---------------------------------------------------------------------------
__device__ float g_y [(size_t)MROWS * FOURH];
__device__ float g_a [(size_t)NCH   * SEQ];
__device__ float g_b [(size_t)NCH   * SEQ];
__device__ float g_hs[(size_t)NCH   * SEQ];
__device__ __half g_xh [(size_t)MROWS * EMB];
__device__ __half g_w1h[(size_t)FOURH * EMB];
__device__ __half g_w2h[(size_t)EMB * HID];
__device__ __half g_gh [(size_t)MROWS * HID];

// ---------------------------------------------------------------------------
// PTX helpers (sm_80-baseline)
// ---------------------------------------------------------------------------
__device__ __forceinline__ uint32_t smem_u32(const void* p) {
    uint32_t a;
    asm("{ .reg .u64 t; cvta.to.shared.u64 t, %1; cvt.u32.u64 %0, t; }" : "=r"(a) : "l"(p));
    return a;
}
__device__ __forceinline__ void cp16(uint32_t s, const void* g) {
    asm volatile("cp.async.cg.shared.global [%0], [%1], 16;" :: "r"(s), "l"(g));
}
#define CP_COMMIT() asm volatile("cp.async.commit_group;" ::: "memory")
#define CP_WAIT(n)  asm volatile("cp.async.wait_group %0;" :: "n"(n) : "memory")

__device__ __forceinline__ void ldsm4(uint32_t& r0, uint32_t& r1, uint32_t& r2, uint32_t& r3,
                                      uint32_t addr) {
    asm volatile("ldmatrix.sync.aligned.m8n8.x4.shared.b16 {%0,%1,%2,%3}, [%4];"
                 : "=r"(r0), "=r"(r1), "=r"(r2), "=r"(r3) : "r"(addr));
}
__device__ __forceinline__ void mma16816(float* c, uint32_t a0, uint32_t a1, uint32_t a2,
                                         uint32_t a3, uint32_t b0, uint32_t b1) {
    asm volatile(
        "mma.sync.aligned.m16n8k16.row.col.f32.f16.f16.f32 "
        "{%0,%1,%2,%3}, {%4,%5,%6,%7}, {%8,%9}, {%0,%1,%2,%3};"
        : "+f"(c[0]), "+f"(c[1]), "+f"(c[2]), "+f"(c[3])
        : "r"(a0), "r"(a1), "r"(a2), "r"(a3), "r"(b0), "r"(b1));
}

// ---------------------------------------------------------------------------
// fp32 -> fp16 round
// ---------------------------------------------------------------------------
__global__ __launch_bounds__(256)
void round1_kernel(const float* __restrict__ in, __half* __restrict__ out, int n4)
{
    int i = blockIdx.x * 256 + threadIdx.x;
    if (i >= n4) return;
    float4 v = ((const float4*)in)[i];
    __half2* op = (__half2*)out;
    op[2*i]   = __half2(__float2half_rn(v.x), __float2half_rn(v.y));
    op[2*i+1] = __half2(__float2half_rn(v.z), __float2half_rn(v.w));
}

// ---------------------------------------------------------------------------
// HMMA fp16 GEMM: C[M,N] = A[M,K] @ B[N,K]^T.
// CTA tile 128x128, BK=32, 3-stage cp.async pipeline (1 sync/iter),
// 256 threads, warp grid 2(M)x4(N), warp tile 64x32, 2 CTAs/SM.
// ---------------------------------------------------------------------------
__global__ __launch_bounds__(GTHREADS, 2)
void gemm_hmma_kernel(const __half* __restrict__ Ah,
                      const __half* __restrict__ Bh,
                      float* __restrict__ C, int N, int K)
{
    constexpr uint32_t B_OFFC = A_MAT;
    constexpr uint32_t STAGE  = A_MAT + B_MATN;   // 20480

    extern __shared__ char smem[];
    const uint32_t sbase = smem_u32(smem);
    const int tid  = threadIdx.x;
    const int wid  = tid >> 5;
    const int lane = tid & 31;
    const int bm = blockIdx.y * BM;
    const int bn = blockIdx.x * BN;
    const int wm = (wid >> 2) * 64;     // 0 or 64
    const int wn = (wid & 3) * 32;      // 0..96

    const int NC = K / BKK;

    const int lrow = tid >> 2;          // 0..63
    const int lch  = tid & 3;
    auto load_stage = [&](int kc, int buf) {
        const uint32_t sb = sbase + buf * STAGE;
        const int k0 = kc * BKK;
#pragma unroll
        for (int j = 0; j < 2; j++) {
            int r = lrow + j * 64;
            size_t goA = (size_t)(bm + r) * K + k0 + lch * 8;
            size_t goB = (size_t)(bn + r) * K + k0 + lch * 8;
            uint32_t so = sb + r * ROWB + lch * 16;
            cp16(so,          Ah + goA);
            cp16(so + B_OFFC, Bh + goB);
        }
    };

    // ldmatrix lane addressing
    const int lr  = lane & 7;
    const int sel = lane >> 3;
    const uint32_t a_lane_off = (uint32_t)((wm + lr + ((sel & 1) << 3)) * ROWB + ((sel >> 1) << 4));
    const uint32_t b_lane_off = (uint32_t)(B_OFFC + (wn + lr + ((sel >> 1) << 3)) * ROWB + ((sel & 1) << 4));

    float acc[4][4][4];
#pragma unroll
    for (int mt = 0; mt < 4; mt++)
#pragma unroll
        for (int nt = 0; nt < 4; nt++)
#pragma unroll
            for (int r = 0; r < 4; r++) acc[mt][nt][r] = 0.f;

    load_stage(0, 0); CP_COMMIT();
    load_stage(1, 1); CP_COMMIT();

    int buf = 0;
    for (int it = 0; it < NC; it++) {
        if (it + 1 < NC) { CP_WAIT(1); } else { CP_WAIT(0); }
        __syncthreads();

        if (it + 2 < NC) { load_stage(it + 2, (buf + 2) % NSTAGE); CP_COMMIT(); }

        const uint32_t sb = sbase + buf * STAGE;
#pragma unroll
        for (int ks = 0; ks < 2; ks++) {
            const uint32_t kofs = ks * 32;
            uint32_t ah[4][4];
#pragma unroll
            for (int mt = 0; mt < 4; mt++) {
                uint32_t addr = sb + a_lane_off + mt * (16 * ROWB) + kofs;
                ldsm4(ah[mt][0], ah[mt][1], ah[mt][2], ah[mt][3], addr);
            }
#pragma unroll
            for (int ng = 0; ng < 2; ng++) {
                uint32_t bh[4];
                uint32_t addr = sb + b_lane_off + ng * (16 * ROWB) + kofs;
                ldsm4(bh[0], bh[1], bh[2], bh[3], addr);
#pragma unroll
                for (int mt = 0; mt < 4; mt++) {
#pragma unroll
                    for (int half = 0; half < 2; half++) {
                        float* a4 = acc[mt][ng * 2 + half];
                        mma16816(a4, ah[mt][0], ah[mt][1], ah[mt][2], ah[mt][3],
                                 bh[half*2], bh[half*2+1]);
                    }
                }
            }
        }
        buf = (buf + 1) % NSTAGE;
    }

    // Epilogue: direct fp32 stores
    const int rrow = lane >> 2;
    const int rcol = (lane & 3) * 2;
#pragma unroll
    for (int mt = 0; mt < 4; mt++) {
        const int row0 = bm + wm + mt * 16 + rrow;
#pragma unroll
        for (int nt = 0; nt < 4; nt++) {
            const int col = bn + wn + nt * 8 + rcol;
            *(float2*)(C + (size_t)row0 * N + col)       = make_float2(acc[mt][nt][0], acc[mt][nt][1]);
            *(float2*)(C + (size_t)(row0 + 8) * N + col) = make_float2(acc[mt][nt][2], acc[mt][nt][3]);
        }
    }
}

// ---------------------------------------------------------------------------
// Conv + gates (per-head f/i split), channel-major outputs  [C, S]
// ---------------------------------------------------------------------------
__global__ __launch_bounds__(256)
void conv_gate_kernel(const float* __restrict__ cw)
{
    __shared__ float s_a[32][33];
    __shared__ float s_b[32][33];

    const int c  = blockIdx.x * 32 + threadIdx.x;
    const int fc = ((c >> 7) << 8) | (c & 127);
    const int ic = fc + 128;
    const int b  = blockIdx.z;
    const int t0 = blockIdx.y * 32;

    float wf[4], wi[4];
#pragma unroll
    for (int k = 0; k < 4; k++) { wf[k] = cw[fc * 4 + k]; wi[k] = cw[ic * 4 + k]; }

#pragma unroll
    for (int it = 0; it < 4; ++it) {
        const int tl = threadIdx.y + it * 8;
        const int t  = t0 + tl;
        const size_t rowbase = ((size_t)(b * SEQ + t)) * FOURH;
        float accf = 0.f, acci = 0.f;
#pragma unroll
        for (int k = 0; k < 4; k++) {
            int tp = t - 3 + k;
            if (tp >= 0) {
                size_t rb2 = ((size_t)(b * SEQ + tp)) * FOURH;
                accf = fmaf(wf[k], g_y[rb2 + 4096 + fc], accf);
                acci = fmaf(wi[k], g_y[rb2 + 4096 + ic], acci);
            }
        }
        const float h = g_y[rowbase + 2048 + c];
        const float f = 1.f / (1.f + __expf(-accf));
        const float i = 1.f / (1.f + __expf(-acci));
        const float denom = 1.f / (f + i + 1e-4f);
        s_a[tl][threadIdx.x] = f * denom;
        s_b[tl][threadIdx.x] = h * i * denom;
    }
    __syncthreads();

    const int lin = threadIdx.y * 32 + threadIdx.x;
    const int tw  = lin & 31;
    const int cb  = lin >> 5;
#pragma unroll
    for (int j = 0; j < 4; j++) {
        const int cl = cb + j * 8;
        const size_t idx = ((size_t)(b * HID + blockIdx.x * 32 + cl)) * SEQ + t0 + tw;
        g_a[idx] = s_a[tw][cl];
        g_b[idx] = s_b[tw][cl];
    }
}

// ---------------------------------------------------------------------------
// Linear scan per channel
// ---------------------------------------------------------------------------
__global__ __launch_bounds__(128)
void scan_kernel()
{
    const int ch  = blockIdx.x;
    const int tid = threadIdx.x;
    const size_t base = (size_t)ch * SEQ + (size_t)tid * 32;

    float a[32], bb[32];
#pragma unroll
    for (int j = 0; j < 32; j += 4) {
        float4 va = *(const float4*)(g_a + base + j);
        float4 vb = *(const float4*)(g_b + base + j);
        a[j+0]=va.x; a[j+1]=va.y; a[j+2]=va.z; a[j+3]=va.w;
        bb[j+0]=vb.x; bb[j+1]=vb.y; bb[j+2]=vb.z; bb[j+3]=vb.w;
    }

    float A = 1.f, Bv = 0.f;
#pragma unroll
    for (int j = 0; j < 32; j++) { Bv = fmaf(a[j], Bv, bb[j]); A *= a[j]; }

    __shared__ float sA[128], sB[128];
    sA[tid] = A; sB[tid] = Bv;
    __syncthreads();
    for (int off = 1; off < 128; off <<= 1) {
        float pA = 0.f, pB = 0.f;
        if (tid >= off) { pA = sA[tid - off]; pB = sB[tid - off]; }
        __syncthreads();
        if (tid >= off) { Bv = fmaf(A, pB, Bv); A = A * pA; sA[tid] = A; sB[tid] = Bv; }
        __syncthreads();
    }

    float h = (tid == 0) ? 0.f : sB[tid - 1];
#pragma unroll
    for (int j = 0; j < 32; j++) { h = fmaf(a[j], h, bb[j]); bb[j] = h; }
#pragma unroll
    for (int j = 0; j < 32; j += 4)
        *(float4*)(g_hs + base + j) = make_float4(bb[j], bb[j+1], bb[j+2], bb[j+3]);
}

// ---------------------------------------------------------------------------
// g = silu(out1) * out2 ; writes fp16 for GEMM2
// ---------------------------------------------------------------------------
__global__ __launch_bounds__(256)
void silu_mul_kernel()
{
    __shared__ float sm[32][33];
    const int c0 = blockIdx.x * 32;
    const int s0 = blockIdx.y * 32;
    const int b  = blockIdx.z;

#pragma unroll
    for (int it = 0; it < 4; ++it) {
        const int cl = threadIdx.y + it * 8;
        const int s  = s0 + threadIdx.x;
        sm[cl][threadIdx.x] = g_hs[((size_t)(b * HID + c0 + cl)) * SEQ + s];
    }
    __syncthreads();

#pragma unroll
    for (int it = 0; it < 4; ++it) {
        const int sl = threadIdx.y + it * 8;
        const int s  = s0 + sl;
        const int c  = c0 + threadIdx.x;
        const size_t row = (size_t)(b * SEQ + s);
        const float o1 = g_y[row * FOURH + c];
        const float sil = o1 / (1.f + __expf(-o1));
        const float v = sil * sm[threadIdx.x][sl];
        g_gh[row * HID + c] = __float2half_rn(v);
    }
}

// ---------------------------------------------------------------------------
// Launch
// ---------------------------------------------------------------------------
extern "C" void kernel_launch(void* const* d_in, const int* in_sizes, int n_in,
                              void* d_out, int out_size)
{
    const float* x  = (const float*)d_in[0];
    const float* w1 = (const float*)d_in[1];
    const float* w2 = (const float*)d_in[2];
    const float* cw = (const float*)d_in[3];
    float* out = (float*)d_out;

    float *yp;
    cudaGetSymbolAddress((void**)&yp, g_y);
    __half *xh, *w1h, *w2h, *gh;
    cudaGetSymbolAddress((void**)&xh,  g_xh);
    cudaGetSymbolAddress((void**)&w1h, g_w1h);
    cudaGetSymbolAddress((void**)&w2h, g_w2h);
    cudaGetSymbolAddress((void**)&gh,  g_gh);

    const int smemg = NSTAGE * (A_MAT + B_MATN);   // 61440
    cudaFuncSetAttribute(gemm_hmma_kernel, cudaFuncAttributeMaxDynamicSharedMemorySize, smemg);

    // conversions
    {
        int n4 = MROWS * EMB / 4;
        round1_kernel<<<(n4 + 255) / 256, 256>>>(x, xh, n4);
        n4 = FOURH * EMB / 4;
        round1_kernel<<<(n4 + 255) / 256, 256>>>(w1, w1h, n4);
        n4 = EMB * HID / 4;
        round1_kernel<<<(n4 + 255) / 256, 256>>>(w2, w2h, n4);
    }

    // GEMM1: y[M,8192] = x @ w1^T
    gemm_hmma_kernel<<<dim3(FOURH / BN, MROWS / BM), GTHREADS, smemg>>>(
        xh, w1h, yp, FOURH, EMB);

    conv_gate_kernel<<<dim3(HID / 32, SEQ / 32, BSZ), dim3(32, 8)>>>(cw);
    scan_kernel<<<NCH, 128>>>();
    silu_mul_kernel<<<dim3(HID / 32, SEQ / 32, BSZ), dim3(32, 8)>>>();

    // GEMM2: out[M,1024] = g @ w2^T
    gemm_hmma_kernel<<<dim3(EMB / BN, MROWS / BM), GTHREADS, smemg>>>(
        gh, w2h, out, EMB, HID);
}

// round 11
// speedup vs baseline: 6.2874x; 1.0933x over previous
#include <cuda_runtime.h>
#include <cuda_fp16.h>
#include <cstdint>

// ---------------------------------------------------------------------------
// Problem constants
// ---------------------------------------------------------------------------
#define BSZ      4
#define SEQ      4096
#define EMB      1024
#define HID      2048
#define FOURH    8192
#define MROWS    (BSZ*SEQ)      // 16384
#define NCH      (BSZ*HID)      // 8192 scan channels

// GEMM tile config (HMMA mma.sync — tcgen05 unavailable at .target sm_103)
#define BM 128
#define BN 128
#define BKK 64
#define ROWB 144                        // 128B data + 16B pad
#define A_MAT (128*ROWB)                // 18432
#define STAGE (2*A_MAT)                 // A + B = 36864
#define NSTAGE 3
#define SMEMG (NSTAGE*STAGE)            // 110592 per CTA (2 CTAs = 221184 <= 227KB/SM)
#define GTHREADS 128

// ---------------------------------------------------------------------------
// Scratch (static device globals)
// ---------------------------------------------------------------------------
__device__ float g_y [(size_t)MROWS * FOURH];
__device__ float g_a [(size_t)NCH   * SEQ];
__device__ float g_b [(size_t)NCH   * SEQ];
__device__ float g_hs[(size_t)NCH   * SEQ];
__device__ __half g_xh [(size_t)MROWS * EMB];
__device__ __half g_w1h[(size_t)FOURH * EMB];
__device__ __half g_w2h[(size_t)EMB * HID];
__device__ __half g_gh [(size_t)MROWS * HID];

// ---------------------------------------------------------------------------
// PTX helpers (sm_80-baseline)
// ---------------------------------------------------------------------------
__device__ __forceinline__ uint32_t smem_u32(const void* p) {
    uint32_t a;
    asm("{ .reg .u64 t; cvta.to.shared.u64 t, %1; cvt.u32.u64 %0, t; }" : "=r"(a) : "l"(p));
    return a;
}
__device__ __forceinline__ void cp16(uint32_t s, const void* g) {
    asm volatile("cp.async.cg.shared.global [%0], [%1], 16;" :: "r"(s), "l"(g));
}
#define CP_COMMIT() asm volatile("cp.async.commit_group;" ::: "memory")
#define CP_WAIT(n)  asm volatile("cp.async.wait_group %0;" :: "n"(n) : "memory")

__device__ __forceinline__ void ldsm4(uint32_t& r0, uint32_t& r1, uint32_t& r2, uint32_t& r3,
                                      uint32_t addr) {
    asm volatile("ldmatrix.sync.aligned.m8n8.x4.shared.b16 {%0,%1,%2,%3}, [%4];"
                 : "=r"(r0), "=r"(r1), "=r"(r2), "=r"(r3) : "r"(addr));
}
__device__ __forceinline__ void mma16816(float* c, uint32_t a0, uint32_t a1, uint32_t a2,
                                         uint32_t a3, uint32_t b0, uint32_t b1) {
    asm volatile(
        "mma.sync.aligned.m16n8k16.row.col.f32.f16.f16.f32 "
        "{%0,%1,%2,%3}, {%4,%5,%6,%7}, {%8,%9}, {%0,%1,%2,%3};"
        : "+f"(c[0]), "+f"(c[1]), "+f"(c[2]), "+f"(c[3])
        : "r"(a0), "r"(a1), "r"(a2), "r"(a3), "r"(b0), "r"(b1));
}

// ---------------------------------------------------------------------------
// fp32 -> fp16 round
// ---------------------------------------------------------------------------
__global__ __launch_bounds__(256)
void round1_kernel(const float* __restrict__ in, __half* __restrict__ out, int n4)
{
    int i = blockIdx.x * 256 + threadIdx.x;
    if (i >= n4) return;
    float4 v = ((const float4*)in)[i];
    __half2* op = (__half2*)out;
    op[2*i]   = __half2(__float2half_rn(v.x), __float2half_rn(v.y));
    op[2*i+1] = __half2(__float2half_rn(v.z), __float2half_rn(v.w));
}

// ---------------------------------------------------------------------------
// HMMA fp16 GEMM: C[M,N] = A[M,K] @ B[N,K]^T.
// CTA tile 128x128, BK=64, 3-stage cp.async pipeline (1 sync/iter),
// 128 threads (4 warps), warp grid 2x2, warp tile 64x64, 2 CTAs/SM.
// ---------------------------------------------------------------------------
__global__ __launch_bounds__(GTHREADS, 2)
void gemm_hmma_kernel(const __half* __restrict__ Ah,
                      const __half* __restrict__ Bh,
                      float* __restrict__ C, int N, int K)
{
    extern __shared__ char smem[];
    const uint32_t sbase = smem_u32(smem);
    const int tid  = threadIdx.x;
    const int wid  = tid >> 5;
    const int lane = tid & 31;
    const int bm = blockIdx.y * BM;
    const int bn = blockIdx.x * BN;
    const int wm = (wid >> 1) * 64;     // 0 or 64
    const int wn = (wid & 1) * 64;      // 0 or 64

    const int NC = K / BKK;

    const int lrow = tid >> 3;          // 0..15
    const int lch  = tid & 7;           // 0..7 (16B chunks, 128B per row)
    auto load_stage = [&](int kc, int buf) {
        const uint32_t sb = sbase + buf * STAGE;
        const int k0 = kc * BKK;
#pragma unroll
        for (int j = 0; j < 8; j++) {
            int r = lrow + j * 16;
            size_t goA = (size_t)(bm + r) * K + k0 + lch * 8;
            size_t goB = (size_t)(bn + r) * K + k0 + lch * 8;
            uint32_t so = sb + r * ROWB + lch * 16;
            cp16(so,         Ah + goA);
            cp16(so + A_MAT, Bh + goB);
        }
    };

    // ldmatrix lane addressing
    const int lr  = lane & 7;
    const int sel = lane >> 3;
    const uint32_t a_lane_off = (uint32_t)((wm + lr + ((sel & 1) << 3)) * ROWB + ((sel >> 1) << 4));
    const uint32_t b_lane_off = (uint32_t)(A_MAT + (wn + lr + ((sel >> 1) << 3)) * ROWB + ((sel & 1) << 4));

    float acc[4][8][4];
#pragma unroll
    for (int mt = 0; mt < 4; mt++)
#pragma unroll
        for (int nt = 0; nt < 8; nt++)
#pragma unroll
            for (int r = 0; r < 4; r++) acc[mt][nt][r] = 0.f;

    load_stage(0, 0); CP_COMMIT();
    load_stage(1, 1); CP_COMMIT();

    int buf = 0;
    for (int it = 0; it < NC; it++) {
        if (it + 1 < NC) { CP_WAIT(1); } else { CP_WAIT(0); }
        __syncthreads();

        if (it + 2 < NC) { load_stage(it + 2, (buf + 2) % NSTAGE); CP_COMMIT(); }

        const uint32_t sb = sbase + buf * STAGE;
#pragma unroll
        for (int ks = 0; ks < 4; ks++) {
            const uint32_t kofs = ks * 32;
            uint32_t ah[4][4];
#pragma unroll
            for (int mt = 0; mt < 4; mt++) {
                uint32_t addr = sb + a_lane_off + mt * (16 * ROWB) + kofs;
                ldsm4(ah[mt][0], ah[mt][1], ah[mt][2], ah[mt][3], addr);
            }
#pragma unroll
            for (int ng = 0; ng < 4; ng++) {
                uint32_t bh[4];
                uint32_t addr = sb + b_lane_off + ng * (16 * ROWB) + kofs;
                ldsm4(bh[0], bh[1], bh[2], bh[3], addr);
#pragma unroll
                for (int mt = 0; mt < 4; mt++) {
#pragma unroll
                    for (int half = 0; half < 2; half++) {
                        float* a4 = acc[mt][ng * 2 + half];
                        mma16816(a4, ah[mt][0], ah[mt][1], ah[mt][2], ah[mt][3],
                                 bh[half*2], bh[half*2+1]);
                    }
                }
            }
        }
        buf = (buf + 1) % NSTAGE;
    }

    // Epilogue: direct fp32 stores
    const int rrow = lane >> 2;
    const int rcol = (lane & 3) * 2;
#pragma unroll
    for (int mt = 0; mt < 4; mt++) {
        const int row0 = bm + wm + mt * 16 + rrow;
#pragma unroll
        for (int nt = 0; nt < 8; nt++) {
            const int col = bn + wn + nt * 8 + rcol;
            *(float2*)(C + (size_t)row0 * N + col)       = make_float2(acc[mt][nt][0], acc[mt][nt][1]);
            *(float2*)(C + (size_t)(row0 + 8) * N + col) = make_float2(acc[mt][nt][2], acc[mt][nt][3]);
        }
    }
}

// ---------------------------------------------------------------------------
// Conv + gates (per-head f/i split), channel-major outputs  [C, S]
// ---------------------------------------------------------------------------
__global__ __launch_bounds__(256)
void conv_gate_kernel(const float* __restrict__ cw)
{
    __shared__ float s_a[32][33];
    __shared__ float s_b[32][33];

    const int c  = blockIdx.x * 32 + threadIdx.x;
    const int fc = ((c >> 7) << 8) | (c & 127);
    const int ic = fc + 128;
    const int b  = blockIdx.z;
    const int t0 = blockIdx.y * 32;

    float wf[4], wi[4];
#pragma unroll
    for (int k = 0; k < 4; k++) { wf[k] = cw[fc * 4 + k]; wi[k] = cw[ic * 4 + k]; }

#pragma unroll
    for (int it = 0; it < 4; ++it) {
        const int tl = threadIdx.y + it * 8;
        const int t  = t0 + tl;
        const size_t rowbase = ((size_t)(b * SEQ + t)) * FOURH;
        float accf = 0.f, acci = 0.f;
#pragma unroll
        for (int k = 0; k < 4; k++) {
            int tp = t - 3 + k;
            if (tp >= 0) {
                size_t rb2 = ((size_t)(b * SEQ + tp)) * FOURH;
                accf = fmaf(wf[k], g_y[rb2 + 4096 + fc], accf);
                acci = fmaf(wi[k], g_y[rb2 + 4096 + ic], acci);
            }
        }
        const float h = g_y[rowbase + 2048 + c];
        const float f = 1.f / (1.f + __expf(-accf));
        const float i = 1.f / (1.f + __expf(-acci));
        const float denom = 1.f / (f + i + 1e-4f);
        s_a[tl][threadIdx.x] = f * denom;
        s_b[tl][threadIdx.x] = h * i * denom;
    }
    __syncthreads();

    const int lin = threadIdx.y * 32 + threadIdx.x;
    const int tw  = lin & 31;
    const int cb  = lin >> 5;
#pragma unroll
    for (int j = 0; j < 4; j++) {
        const int cl = cb + j * 8;
        const size_t idx = ((size_t)(b * HID + blockIdx.x * 32 + cl)) * SEQ + t0 + tw;
        g_a[idx] = s_a[tw][cl];
        g_b[idx] = s_b[tw][cl];
    }
}

// ---------------------------------------------------------------------------
// Linear scan per channel
// ---------------------------------------------------------------------------
__global__ __launch_bounds__(128)
void scan_kernel()
{
    const int ch  = blockIdx.x;
    const int tid = threadIdx.x;
    const size_t base = (size_t)ch * SEQ + (size_t)tid * 32;

    float a[32], bb[32];
#pragma unroll
    for (int j = 0; j < 32; j += 4) {
        float4 va = *(const float4*)(g_a + base + j);
        float4 vb = *(const float4*)(g_b + base + j);
        a[j+0]=va.x; a[j+1]=va.y; a[j+2]=va.z; a[j+3]=va.w;
        bb[j+0]=vb.x; bb[j+1]=vb.y; bb[j+2]=vb.z; bb[j+3]=vb.w;
    }

    float A = 1.f, Bv = 0.f;
#pragma unroll
    for (int j = 0; j < 32; j++) { Bv = fmaf(a[j], Bv, bb[j]); A *= a[j]; }

    __shared__ float sA[128], sB[128];
    sA[tid] = A; sB[tid] = Bv;
    __syncthreads();
    for (int off = 1; off < 128; off <<= 1) {
        float pA = 0.f, pB = 0.f;
        if (tid >= off) { pA = sA[tid - off]; pB = sB[tid - off]; }
        __syncthreads();
        if (tid >= off) { Bv = fmaf(A, pB, Bv); A = A * pA; sA[tid] = A; sB[tid] = Bv; }
        __syncthreads();
    }

    float h = (tid == 0) ? 0.f : sB[tid - 1];
#pragma unroll
    for (int j = 0; j < 32; j++) { h = fmaf(a[j], h, bb[j]); bb[j] = h; }
#pragma unroll
    for (int j = 0; j < 32; j += 4)
        *(float4*)(g_hs + base + j) = make_float4(bb[j], bb[j+1], bb[j+2], bb[j+3]);
}

// ---------------------------------------------------------------------------
// g = silu(out1) * out2 ; writes fp16 for GEMM2
// ---------------------------------------------------------------------------
__global__ __launch_bounds__(256)
void silu_mul_kernel()
{
    __shared__ float sm[32][33];
    const int c0 = blockIdx.x * 32;
    const int s0 = blockIdx.y * 32;
    const int b  = blockIdx.z;

#pragma unroll
    for (int it = 0; it < 4; ++it) {
        const int cl = threadIdx.y + it * 8;
        const int s  = s0 + threadIdx.x;
        sm[cl][threadIdx.x] = g_hs[((size_t)(b * HID + c0 + cl)) * SEQ + s];
    }
    __syncthreads();

#pragma unroll
    for (int it = 0; it < 4; ++it) {
        const int sl = threadIdx.y + it * 8;
        const int s  = s0 + sl;
        const int c  = c0 + threadIdx.x;
        const size_t row = (size_t)(b * SEQ + s);
        const float o1 = g_y[row * FOURH + c];
        const float sil = o1 / (1.f + __expf(-o1));
        const float v = sil * sm[threadIdx.x][sl];
        g_gh[row * HID + c] = __float2half_rn(v);
    }
}

// ---------------------------------------------------------------------------
// Launch
// ---------------------------------------------------------------------------
extern "C" void kernel_launch(void* const* d_in, const int* in_sizes, int n_in,
                              void* d_out, int out_size)
{
    const float* x  = (const float*)d_in[0];
    const float* w1 = (const float*)d_in[1];
    const float* w2 = (const float*)d_in[2];
    const float* cw = (const float*)d_in[3];
    float* out = (float*)d_out;

    float *yp;
    cudaGetSymbolAddress((void**)&yp, g_y);
    __half *xh, *w1h, *w2h, *gh;
    cudaGetSymbolAddress((void**)&xh,  g_xh);
    cudaGetSymbolAddress((void**)&w1h, g_w1h);
    cudaGetSymbolAddress((void**)&w2h, g_w2h);
    cudaGetSymbolAddress((void**)&gh,  g_gh);

    cudaFuncSetAttribute(gemm_hmma_kernel, cudaFuncAttributeMaxDynamicSharedMemorySize, SMEMG);

    // conversions
    {
        int n4 = MROWS * EMB / 4;
        round1_kernel<<<(n4 + 255) / 256, 256>>>(x, xh, n4);
        n4 = FOURH * EMB / 4;
        round1_kernel<<<(n4 + 255) / 256, 256>>>(w1, w1h, n4);
        n4 = EMB * HID / 4;
        round1_kernel<<<(n4 + 255) / 256, 256>>>(w2, w2h, n4);
    }

    // GEMM1: y[M,8192] = x @ w1^T
    gemm_hmma_kernel<<<dim3(FOURH / BN, MROWS / BM), GTHREADS, SMEMG>>>(
        xh, w1h, yp, FOURH, EMB);

    conv_gate_kernel<<<dim3(HID / 32, SEQ / 32, BSZ), dim3(32, 8)>>>(cw);
    scan_kernel<<<NCH, 128>>>();
    silu_mul_kernel<<<dim3(HID / 32, SEQ / 32, BSZ), dim3(32, 8)>>>();

    // GEMM2: out[M,1024] = g @ w2^T
    gemm_hmma_kernel<<<dim3(EMB / BN, MROWS / BM), GTHREADS, SMEMG>>>(
        gh, w2h, out, EMB, HID);
}